// round 1
// baseline (speedup 1.0000x reference)
#include <cuda_runtime.h>
#include <math.h>

#define N_NODES 50000
#define N_EDGES 800000
#define H 64

// Scratch for scatter-sum of gated messages (no allocs allowed -> device global).
__device__ float g_msum[N_NODES * H];

// ---------------------------------------------------------------------------
// Zero the message-accumulator buffer (float4 vectorized).
// ---------------------------------------------------------------------------
__global__ void zero_msum_kernel() {
    int i = blockIdx.x * blockDim.x + threadIdx.x;
    const int n4 = N_NODES * H / 4;
    if (i < n4) {
        reinterpret_cast<float4*>(g_msum)[i] = make_float4(0.f, 0.f, 0.f, 0.f);
    }
}

// ---------------------------------------------------------------------------
// Edge kernel: warp per edge.
//   msg_in = [feat[src] (64) | feat[dst] (64) | sqdist (1)]  (129)
//   h1 = relu(msg_in @ W1 + b1)        (129 -> 64)
//   m  = relu(h1 @ W2 + b2)            (64  -> 64)
//   g  = sigmoid(m . we + be)
//   atomicAdd(g_msum[dst], m * g)
// Weights live in dynamic shared memory (loaded once per block).
// Lane l owns output channels 2l and 2l+1 (float2 weight loads).
// ---------------------------------------------------------------------------

// dynamic smem layout (floats):
//   sW1  : [0, 8256)          129*64
//   sW2  : [8256, 12352)      64*64
//   swe  : [12352, 12416)     64
//   sb1  : [12416, 12480)
//   sb2  : [12480, 12544)
//   sbe  : [12544, 12552)     (1 used, padded for alignment)
//   warp bufs: 8 * (132 msg + 64 hbuf) starting at 12552
#define EDGE_SMEM_FLOATS (12552 + 8 * 196)
#define EDGE_SMEM_BYTES  (EDGE_SMEM_FLOATS * 4)

__global__ __launch_bounds__(256) void edge_kernel(
    const float* __restrict__ feat, const float* __restrict__ x,
    const int*   __restrict__ src,  const int*   __restrict__ dst,
    const float* __restrict__ W1,   const float* __restrict__ b1,
    const float* __restrict__ W2,   const float* __restrict__ b2,
    const float* __restrict__ we,   const float* __restrict__ be)
{
    extern __shared__ float sm[];
    float* sW1 = sm;
    float* sW2 = sm + 8256;
    float* swe = sm + 12352;
    float* sb1 = sm + 12416;
    float* sb2 = sm + 12480;
    float* sbe = sm + 12544;

    const int tid = threadIdx.x;
    for (int i = tid; i < 129 * 64; i += 256) sW1[i] = W1[i];
    for (int i = tid; i < 64 * 64;  i += 256) sW2[i] = W2[i];
    if (tid < 64) { swe[tid] = we[tid]; sb1[tid] = b1[tid]; sb2[tid] = b2[tid]; }
    if (tid == 0) sbe[0] = be[0];
    __syncthreads();

    const int w = tid >> 5;
    const int l = tid & 31;
    float* msg  = sm + 12552 + w * 196;   // 132 floats (129 used)
    float* hbuf = msg + 132;              // 64 floats, 8B-aligned index

    const float2* w1v = reinterpret_cast<const float2*>(sW1);
    const float2* w2v = reinterpret_cast<const float2*>(sW2);
    const float bias1a = sb1[2 * l], bias1b = sb1[2 * l + 1];
    const float bias2a = sb2[2 * l], bias2b = sb2[2 * l + 1];
    const float wea = swe[2 * l], web = swe[2 * l + 1];
    const float be0 = sbe[0];

    const int warp_global = blockIdx.x * 8 + w;
    const int nwarps = gridDim.x * 8;

    for (int e = warp_global; e < N_EDGES; e += nwarps) {
        const int s = src[e];
        const int d = dst[e];

        // squared distance (all lanes compute redundantly; broadcast loads)
        float dx0 = x[s * 3 + 0] - x[d * 3 + 0];
        float dx1 = x[s * 3 + 1] - x[d * 3 + 1];
        float dx2 = x[s * 3 + 2] - x[d * 3 + 2];
        float sqd = dx0 * dx0 + dx1 * dx1 + dx2 * dx2;

        // stage msg_in for this edge into shared (warp-private buffer)
        msg[l]      = feat[(size_t)s * 64 + l];
        msg[32 + l] = feat[(size_t)s * 64 + 32 + l];
        msg[64 + l] = feat[(size_t)d * 64 + l];
        msg[96 + l] = feat[(size_t)d * 64 + 32 + l];
        if (l == 0) msg[128] = sqd;
        __syncwarp();

        // layer 1: 129 -> 64, relu
        float a0 = bias1a, a1 = bias1b;
        #pragma unroll 4
        for (int k = 0; k < 129; k++) {
            float mk = msg[k];
            float2 wv = w1v[k * 32 + l];
            a0 = fmaf(mk, wv.x, a0);
            a1 = fmaf(mk, wv.y, a1);
        }
        a0 = fmaxf(a0, 0.f);
        a1 = fmaxf(a1, 0.f);
        reinterpret_cast<float2*>(hbuf)[l] = make_float2(a0, a1);
        __syncwarp();

        // layer 2: 64 -> 64, relu
        float m0 = bias2a, m1 = bias2b;
        #pragma unroll 4
        for (int k = 0; k < 64; k++) {
            float hk = hbuf[k];
            float2 wv = w2v[k * 32 + l];
            m0 = fmaf(hk, wv.x, m0);
            m1 = fmaf(hk, wv.y, m1);
        }
        m0 = fmaxf(m0, 0.f);
        m1 = fmaxf(m1, 0.f);

        // soft edge gate
        float p = m0 * wea + m1 * web;
        #pragma unroll
        for (int off = 16; off > 0; off >>= 1)
            p += __shfl_xor_sync(0xffffffffu, p, off);
        float g = 1.f / (1.f + expf(-(p + be0)));

        // scatter gated message
        float* outp = g_msum + (size_t)d * 64 + 2 * l;
        atomicAdd(outp,     m0 * g);
        atomicAdd(outp + 1, m1 * g);
        __syncwarp();   // protect msg/hbuf reuse across iterations
    }
}

// ---------------------------------------------------------------------------
// Node kernel: warp per node.
//   h = m_sum + feat
//   out = relu(h @ U1 + c1) @ U2 + c2 + feat
// ---------------------------------------------------------------------------
__global__ __launch_bounds__(256) void node_kernel(
    const float* __restrict__ feat,
    const float* __restrict__ U1, const float* __restrict__ c1,
    const float* __restrict__ U2, const float* __restrict__ c2,
    float* __restrict__ out)
{
    __shared__ float sU1[64 * 64];
    __shared__ float sU2[64 * 64];
    __shared__ float sc1[64];
    __shared__ float sc2[64];
    __shared__ float buf[8][128];   // per warp: nbuf[64] + hbuf[64]

    const int tid = threadIdx.x;
    for (int i = tid; i < 64 * 64; i += 256) { sU1[i] = U1[i]; sU2[i] = U2[i]; }
    if (tid < 64) { sc1[tid] = c1[tid]; sc2[tid] = c2[tid]; }
    __syncthreads();

    const int w = tid >> 5;
    const int l = tid & 31;
    float* nbuf = buf[w];
    float* hb   = buf[w] + 64;

    const float2* u1v = reinterpret_cast<const float2*>(sU1);
    const float2* u2v = reinterpret_cast<const float2*>(sU2);
    const float c1a = sc1[2 * l], c1b = sc1[2 * l + 1];
    const float c2a = sc2[2 * l], c2b = sc2[2 * l + 1];

    for (int n = blockIdx.x * 8 + w; n < N_NODES; n += gridDim.x * 8) {
        const float2 f = reinterpret_cast<const float2*>(feat + (size_t)n * 64)[l];
        const float2 ms = reinterpret_cast<const float2*>(g_msum + (size_t)n * 64)[l];
        reinterpret_cast<float2*>(nbuf)[l] = make_float2(ms.x + f.x, ms.y + f.y);
        __syncwarp();

        float a0 = c1a, a1 = c1b;
        #pragma unroll 4
        for (int k = 0; k < 64; k++) {
            float vk = nbuf[k];
            float2 uv = u1v[k * 32 + l];
            a0 = fmaf(vk, uv.x, a0);
            a1 = fmaf(vk, uv.y, a1);
        }
        a0 = fmaxf(a0, 0.f);
        a1 = fmaxf(a1, 0.f);
        reinterpret_cast<float2*>(hb)[l] = make_float2(a0, a1);
        __syncwarp();

        float o0 = c2a, o1 = c2b;
        #pragma unroll 4
        for (int k = 0; k < 64; k++) {
            float hk = hb[k];
            float2 uv = u2v[k * 32 + l];
            o0 = fmaf(hk, uv.x, o0);
            o1 = fmaf(hk, uv.y, o1);
        }
        reinterpret_cast<float2*>(out + (size_t)n * 64)[l] =
            make_float2(o0 + f.x, o1 + f.y);
        __syncwarp();
    }
}

// ---------------------------------------------------------------------------
// kernel_launch
// inputs (metadata order): feat, x, src, dst, W1, b1, W2, b2, we, be, U1, c1, U2, c2
// ---------------------------------------------------------------------------
extern "C" void kernel_launch(void* const* d_in, const int* in_sizes, int n_in,
                              void* d_out, int out_size)
{
    const float* feat = (const float*)d_in[0];
    const float* x    = (const float*)d_in[1];
    const int*   src  = (const int*)  d_in[2];
    const int*   dst  = (const int*)  d_in[3];
    const float* W1   = (const float*)d_in[4];
    const float* b1   = (const float*)d_in[5];
    const float* W2   = (const float*)d_in[6];
    const float* b2   = (const float*)d_in[7];
    const float* we   = (const float*)d_in[8];
    const float* be   = (const float*)d_in[9];
    const float* U1   = (const float*)d_in[10];
    const float* c1   = (const float*)d_in[11];
    const float* U2   = (const float*)d_in[12];
    const float* c2   = (const float*)d_in[13];
    float* out = (float*)d_out;

    // > 48 KB dynamic smem for the edge kernel
    cudaFuncSetAttribute(edge_kernel,
                         cudaFuncAttributeMaxDynamicSharedMemorySize,
                         EDGE_SMEM_BYTES);

    // 1) zero the scatter accumulator
    {
        const int n4 = N_NODES * H / 4;
        zero_msum_kernel<<<(n4 + 255) / 256, 256>>>();
    }
    // 2) edge phase (grid-stride, 8 warps/block)
    edge_kernel<<<1184, 256, EDGE_SMEM_BYTES>>>(feat, x, src, dst,
                                                W1, b1, W2, b2, we, be);
    // 3) node phase
    node_kernel<<<1184, 256>>>(feat, U1, c1, U2, c2, out);
}

// round 2
// speedup vs baseline: 2.2125x; 2.2125x over previous
#include <cuda_runtime.h>
#include <math.h>

#define N_NODES 50000
#define N_EDGES 800000
#define H 64
#define TILE_E 128
#define N_TILES (N_EDGES / TILE_E)   // 6250 exactly
#define THREADS 512

// Scatter accumulator (no allocs allowed -> device global).
__device__ float g_msum[N_NODES * H];

typedef unsigned long long u64;

__device__ __forceinline__ u64 pk(float lo, float hi) {
    u64 r; asm("mov.b64 %0, {%1, %2};" : "=l"(r) : "f"(lo), "f"(hi)); return r;
}
__device__ __forceinline__ void upk(float& lo, float& hi, u64 v) {
    asm("mov.b64 {%0, %1}, %2;" : "=f"(lo), "=f"(hi) : "l"(v));
}
// packed fp32x2 FMA (Blackwell): d = a*b + c on both 32-bit halves
__device__ __forceinline__ u64 fma2(u64 a, u64 b, u64 c) {
    u64 d; asm("fma.rn.f32x2 %0, %1, %2, %3;" : "=l"(d) : "l"(a), "l"(b), "l"(c));
    return d;
}
__device__ __forceinline__ void red4(float* p, float a, float b, float c, float d) {
    asm volatile("red.global.add.v4.f32 [%0], {%1,%2,%3,%4};"
                 :: "l"(p), "f"(a), "f"(b), "f"(c), "f"(d) : "memory");
}

// ---------------------------------------------------------------------------
__global__ void zero_msum_kernel() {
    int i = blockIdx.x * blockDim.x + threadIdx.x;
    const int n4 = N_NODES * H / 4;
    if (i < n4)
        reinterpret_cast<float4*>(g_msum)[i] = make_float4(0.f, 0.f, 0.f, 0.f);
}

// ---------------------------------------------------------------------------
// Edge kernel: persistent, one CTA/SM, 128-edge tiles.
// smem layout (floats):
//   sW1 [129][64]        : 0      .. 8256
//   sW2 [64][64]         : 8256   .. 12352
//   b1/b2/we/be          : 12352  .. 12552
//   union region         : 12552:
//     A1 [129][132]      : 17028 floats   (msg tile, [k][e])
//     sH [64][132]       : first 8448     (h1 tile, [k][e], overlays A1)
//     sM [128][68]       : next  8704     (m tile, [e][j], overlays A1)
//   sG [128][17]         : 29704 .. 31880 (gate partials)
//   sGate [128]          : 31880 .. 32008
// ---------------------------------------------------------------------------
#define OFF_W1   0
#define OFF_W2   8256
#define OFF_B1   12352
#define OFF_B2   12416
#define OFF_WE   12480
#define OFF_BE   12544
#define OFF_U    12552
#define OFF_H    OFF_U
#define OFF_M    (OFF_U + 8448)
#define OFF_G    (OFF_U + 17152)
#define OFF_GATE (OFF_G + 128 * 17)
#define EDGE_SMEM_FLOATS (OFF_GATE + 128)
#define EDGE_SMEM_BYTES  (EDGE_SMEM_FLOATS * 4)

__global__ __launch_bounds__(THREADS, 1) void edge_kernel(
    const float* __restrict__ feat, const float* __restrict__ x,
    const int*   __restrict__ src,  const int*   __restrict__ dst,
    const float* __restrict__ W1,   const float* __restrict__ b1,
    const float* __restrict__ W2,   const float* __restrict__ b2,
    const float* __restrict__ we,   const float* __restrict__ be)
{
    extern __shared__ float sm[];
    float* sW1   = sm + OFF_W1;
    float* sW2   = sm + OFF_W2;
    float* sb1   = sm + OFF_B1;
    float* sb2   = sm + OFF_B2;
    float* swe   = sm + OFF_WE;
    float* sbe   = sm + OFF_BE;
    float* A1    = sm + OFF_U;     // stride 132
    float* sH    = sm + OFF_H;     // stride 132
    float* sM    = sm + OFF_M;     // stride 68
    float* sG    = sm + OFF_G;     // stride 17
    float* sGate = sm + OFF_GATE;

    const int tid = threadIdx.x;
    for (int i = tid; i < 129 * 64; i += THREADS) sW1[i] = W1[i];
    for (int i = tid; i < 64 * 64;  i += THREADS) sW2[i] = W2[i];
    if (tid < 64) { sb1[tid] = b1[tid]; sb2[tid] = b2[tid]; swe[tid] = we[tid]; }
    if (tid == 0) sbe[0] = be[0];
    __syncthreads();

    const int tr = tid >> 4;       // 0..31 : edge group (4 edges)
    const int tc = tid & 15;       // 0..15 : col group (4 cols)
    const int er = tr * 4;
    const int jc = tc * 4;

    // packed biases for accumulator init
    const u64 pb1_0 = pk(sb1[jc+0], sb1[jc+0]);
    const u64 pb1_1 = pk(sb1[jc+1], sb1[jc+1]);
    const u64 pb1_2 = pk(sb1[jc+2], sb1[jc+2]);
    const u64 pb1_3 = pk(sb1[jc+3], sb1[jc+3]);
    const u64 pb2_0 = pk(sb2[jc+0], sb2[jc+0]);
    const u64 pb2_1 = pk(sb2[jc+1], sb2[jc+1]);
    const u64 pb2_2 = pk(sb2[jc+2], sb2[jc+2]);
    const u64 pb2_3 = pk(sb2[jc+3], sb2[jc+3]);
    const float we0 = swe[jc+0], we1 = swe[jc+1], we2 = swe[jc+2], we3 = swe[jc+3];
    const float be0 = sbe[0];

    const int ge = tid >> 2;       // 0..127 (gather/scatter edge)
    const int gp = tid & 3;        // 0..3   (gather k-phase / scatter j-quarter)

    for (int tile = blockIdx.x; tile < N_TILES; tile += gridDim.x) {
        const int e0 = tile * TILE_E;

        // -------- gather msg_in -> A1 [k][e] (k interleaved by gp) --------
        {
            const int s = src[e0 + ge];
            const int d = dst[e0 + ge];
            const float* fs = feat + (size_t)s * 64;
            const float* fd = feat + (size_t)d * 64;
            #pragma unroll
            for (int i = 0; i < 16; i++) {
                int k = gp + 4 * i;
                A1[k * 132 + ge] = fs[k];
            }
            #pragma unroll
            for (int i = 0; i < 16; i++) {
                int k = gp + 4 * i;
                A1[(64 + k) * 132 + ge] = fd[k];
            }
            if (gp == 0) {
                float dx = x[s*3+0] - x[d*3+0];
                float dy = x[s*3+1] - x[d*3+1];
                float dz = x[s*3+2] - x[d*3+2];
                A1[128 * 132 + ge] = dx*dx + dy*dy + dz*dz;
            }
        }
        __syncthreads();

        // -------- layer 1: [128,129] @ [129,64], relu --------
        u64 c00 = pb1_0, c01 = pb1_1, c02 = pb1_2, c03 = pb1_3;  // edges (e0,e1)
        u64 c10 = pb1_0, c11 = pb1_1, c12 = pb1_2, c13 = pb1_3;  // edges (e2,e3)
        #pragma unroll 4
        for (int k = 0; k < 129; k++) {
            float4 av = *reinterpret_cast<const float4*>(&A1[k * 132 + er]);
            float4 bv = *reinterpret_cast<const float4*>(&sW1[k * 64 + jc]);
            u64 a0 = pk(av.x, av.y), a1 = pk(av.z, av.w);
            u64 b0 = pk(bv.x, bv.x), b1v = pk(bv.y, bv.y);
            u64 b2v = pk(bv.z, bv.z), b3 = pk(bv.w, bv.w);
            c00 = fma2(a0, b0, c00);  c10 = fma2(a1, b0, c10);
            c01 = fma2(a0, b1v, c01); c11 = fma2(a1, b1v, c11);
            c02 = fma2(a0, b2v, c02); c12 = fma2(a1, b2v, c12);
            c03 = fma2(a0, b3, c03);  c13 = fma2(a1, b3, c13);
        }
        float v[4][4];  // [edge][col]
        upk(v[0][0], v[1][0], c00); upk(v[0][1], v[1][1], c01);
        upk(v[0][2], v[1][2], c02); upk(v[0][3], v[1][3], c03);
        upk(v[2][0], v[3][0], c10); upk(v[2][1], v[3][1], c11);
        upk(v[2][2], v[3][2], c12); upk(v[2][3], v[3][3], c13);
        #pragma unroll
        for (int i = 0; i < 4; i++)
            #pragma unroll
            for (int j = 0; j < 4; j++)
                v[i][j] = fmaxf(v[i][j], 0.f);
        __syncthreads();   // all layer-1 reads of A1 done before sH overlays it

        // store h1 transposed: sH[j][e]
        #pragma unroll
        for (int j = 0; j < 4; j++)
            *reinterpret_cast<float4*>(&sH[(jc + j) * 132 + er]) =
                make_float4(v[0][j], v[1][j], v[2][j], v[3][j]);
        __syncthreads();

        // -------- layer 2: [128,64] @ [64,64], relu --------
        c00 = pb2_0; c01 = pb2_1; c02 = pb2_2; c03 = pb2_3;
        c10 = pb2_0; c11 = pb2_1; c12 = pb2_2; c13 = pb2_3;
        #pragma unroll 4
        for (int k = 0; k < 64; k++) {
            float4 av = *reinterpret_cast<const float4*>(&sH[k * 132 + er]);
            float4 bv = *reinterpret_cast<const float4*>(&sW2[k * 64 + jc]);
            u64 a0 = pk(av.x, av.y), a1 = pk(av.z, av.w);
            u64 b0 = pk(bv.x, bv.x), b1v = pk(bv.y, bv.y);
            u64 b2v = pk(bv.z, bv.z), b3 = pk(bv.w, bv.w);
            c00 = fma2(a0, b0, c00);  c10 = fma2(a1, b0, c10);
            c01 = fma2(a0, b1v, c01); c11 = fma2(a1, b1v, c11);
            c02 = fma2(a0, b2v, c02); c12 = fma2(a1, b2v, c12);
            c03 = fma2(a0, b3, c03);  c13 = fma2(a1, b3, c13);
        }
        upk(v[0][0], v[1][0], c00); upk(v[0][1], v[1][1], c01);
        upk(v[0][2], v[1][2], c02); upk(v[0][3], v[1][3], c03);
        upk(v[2][0], v[3][0], c10); upk(v[2][1], v[3][1], c11);
        upk(v[2][2], v[3][2], c12); upk(v[2][3], v[3][3], c13);
        #pragma unroll
        for (int i = 0; i < 4; i++)
            #pragma unroll
            for (int j = 0; j < 4; j++)
                v[i][j] = fmaxf(v[i][j], 0.f);

        // gate partials + m tile stores
        #pragma unroll
        for (int i = 0; i < 4; i++) {
            float p = v[i][0]*we0 + v[i][1]*we1 + v[i][2]*we2 + v[i][3]*we3;
            sG[(er + i) * 17 + tc] = p;
            *reinterpret_cast<float4*>(&sM[(er + i) * 68 + jc]) =
                make_float4(v[i][0], v[i][1], v[i][2], v[i][3]);
        }
        __syncthreads();

        // gate reduce (128 threads, one per edge)
        if (tid < 128) {
            float acc = be0;
            #pragma unroll
            for (int t = 0; t < 16; t++) acc += sG[tid * 17 + t];
            sGate[tid] = 1.f / (1.f + expf(-acc));
        }
        __syncthreads();

        // -------- scatter: g_msum[dst] += m * gate (red.v4) --------
        {
            const float g = sGate[ge];
            const int d = dst[e0 + ge];
            float* base = g_msum + (size_t)d * 64 + gp * 16;
            const float* mrow = &sM[ge * 68 + gp * 16];
            #pragma unroll
            for (int i = 0; i < 4; i++) {
                float4 mv = *reinterpret_cast<const float4*>(&mrow[4 * i]);
                red4(base + 4 * i, mv.x * g, mv.y * g, mv.z * g, mv.w * g);
            }
        }
        __syncthreads();   // protect A1/sM reuse next tile
    }
}

// ---------------------------------------------------------------------------
// Node kernel: warp per node (small vs edge phase).
// ---------------------------------------------------------------------------
__global__ __launch_bounds__(256) void node_kernel(
    const float* __restrict__ feat,
    const float* __restrict__ U1, const float* __restrict__ c1,
    const float* __restrict__ U2, const float* __restrict__ c2,
    float* __restrict__ out)
{
    __shared__ float sU1[64 * 64];
    __shared__ float sU2[64 * 64];
    __shared__ float sc1[64];
    __shared__ float sc2[64];
    __shared__ float buf[8][128];

    const int tid = threadIdx.x;
    for (int i = tid; i < 64 * 64; i += 256) { sU1[i] = U1[i]; sU2[i] = U2[i]; }
    if (tid < 64) { sc1[tid] = c1[tid]; sc2[tid] = c2[tid]; }
    __syncthreads();

    const int w = tid >> 5;
    const int l = tid & 31;
    float* nbuf = buf[w];
    float* hb   = buf[w] + 64;

    const float2* u1v = reinterpret_cast<const float2*>(sU1);
    const float2* u2v = reinterpret_cast<const float2*>(sU2);
    const float c1a = sc1[2 * l], c1b = sc1[2 * l + 1];
    const float c2a = sc2[2 * l], c2b = sc2[2 * l + 1];

    for (int n = blockIdx.x * 8 + w; n < N_NODES; n += gridDim.x * 8) {
        const float2 f  = reinterpret_cast<const float2*>(feat + (size_t)n * 64)[l];
        const float2 ms = reinterpret_cast<const float2*>(g_msum + (size_t)n * 64)[l];
        reinterpret_cast<float2*>(nbuf)[l] = make_float2(ms.x + f.x, ms.y + f.y);
        __syncwarp();

        float a0 = c1a, a1 = c1b;
        #pragma unroll 4
        for (int k = 0; k < 64; k++) {
            float vk = nbuf[k];
            float2 uv = u1v[k * 32 + l];
            a0 = fmaf(vk, uv.x, a0);
            a1 = fmaf(vk, uv.y, a1);
        }
        a0 = fmaxf(a0, 0.f);
        a1 = fmaxf(a1, 0.f);
        reinterpret_cast<float2*>(hb)[l] = make_float2(a0, a1);
        __syncwarp();

        float o0 = c2a, o1 = c2b;
        #pragma unroll 4
        for (int k = 0; k < 64; k++) {
            float hk = hb[k];
            float2 uv = u2v[k * 32 + l];
            o0 = fmaf(hk, uv.x, o0);
            o1 = fmaf(hk, uv.y, o1);
        }
        reinterpret_cast<float2*>(out + (size_t)n * 64)[l] =
            make_float2(o0 + f.x, o1 + f.y);
        __syncwarp();
    }
}

// ---------------------------------------------------------------------------
extern "C" void kernel_launch(void* const* d_in, const int* in_sizes, int n_in,
                              void* d_out, int out_size)
{
    const float* feat = (const float*)d_in[0];
    const float* x    = (const float*)d_in[1];
    const int*   src  = (const int*)  d_in[2];
    const int*   dst  = (const int*)  d_in[3];
    const float* W1   = (const float*)d_in[4];
    const float* b1   = (const float*)d_in[5];
    const float* W2   = (const float*)d_in[6];
    const float* b2   = (const float*)d_in[7];
    const float* we   = (const float*)d_in[8];
    const float* be   = (const float*)d_in[9];
    const float* U1   = (const float*)d_in[10];
    const float* c1   = (const float*)d_in[11];
    const float* U2   = (const float*)d_in[12];
    const float* c2   = (const float*)d_in[13];
    float* out = (float*)d_out;

    cudaFuncSetAttribute(edge_kernel,
                         cudaFuncAttributeMaxDynamicSharedMemorySize,
                         EDGE_SMEM_BYTES);

    {
        const int n4 = N_NODES * H / 4;
        zero_msum_kernel<<<(n4 + 255) / 256, 256>>>();
    }
    edge_kernel<<<148, THREADS, EDGE_SMEM_BYTES>>>(feat, x, src, dst,
                                                   W1, b1, W2, b2, we, be);
    node_kernel<<<1184, 256>>>(feat, U1, c1, U2, c2, out);
}

// round 5
// speedup vs baseline: 3.5634x; 1.6106x over previous
#include <cuda_runtime.h>
#include <math.h>
#include <cstdint>

#define N_NODES 50000
#define N_EDGES 800000
#define TILE_E  128
#define N_TILES (N_EDGES / TILE_E)   // 6250
#define THREADS 512
#define NCTAS   152

// strides (in floats)
#define SA_STR  140     // A1 rows: positions 0..135 (k-permuted), ≡12 mod 32
#define SW1_STR 136     // W1 rows (n=64): positions 0..135, ≡8 mod 32
#define SH_STR  68      // H rows: positions 0..63, ≡4 mod 32
#define SW2_STR 68

// smem word offsets
#define O_A0   0
#define O_A1   (O_A0 + 128 * SA_STR)          // 17920
#define O_W1   (O_A1 + 128 * SA_STR)          // 35840
#define O_H    (O_W1 + 64 * SW1_STR)          // 44544
#define O_W2   (O_H  + 128 * SH_STR)          // 53248
#define O_B1   (O_W2 + 64 * SW2_STR)          // 57600
#define O_B2   (O_B1 + 64)
#define O_WE   (O_B2 + 64)
#define O_BE   (O_WE + 64)
#define SMEM_WORDS (O_BE + 8)
#define SMEM_BYTES (SMEM_WORDS * 4)           // 231,232 B <= 232,448

// Scatter accumulator (no allocs -> device global).
__device__ float g_msum[N_NODES * 64];

// k-permutation within each 8-group: k = k0 + h*4 + l  ->  pos = k0 + 2*l + h
__host__ __device__ __forceinline__ int kpos(int k) {
    return (k & ~7) + 2 * (k & 3) + ((k >> 2) & 1);
}

__device__ __forceinline__ uint32_t tf32r(float f) {
    uint32_t r; asm("cvt.rna.tf32.f32 %0, %1;" : "=r"(r) : "f"(f)); return r;
}
__device__ __forceinline__ void mma8(float d[4], uint32_t a0, uint32_t a1,
                                     uint32_t a2, uint32_t a3,
                                     uint32_t b0, uint32_t b1) {
    asm("mma.sync.aligned.m16n8k8.row.col.f32.tf32.tf32.f32 "
        "{%0,%1,%2,%3}, {%4,%5,%6,%7}, {%8,%9}, {%0,%1,%2,%3};"
        : "+f"(d[0]), "+f"(d[1]), "+f"(d[2]), "+f"(d[3])
        : "r"(a0), "r"(a1), "r"(a2), "r"(a3), "r"(b0), "r"(b1));
}
__device__ __forceinline__ void red2(float* p, float a, float b) {
    asm volatile("red.global.add.v2.f32 [%0], {%1,%2};"
                 :: "l"(p), "f"(a), "f"(b) : "memory");
}

// ---------------------------------------------------------------------------
__global__ void zero_msum_kernel() {
    int i = blockIdx.x * blockDim.x + threadIdx.x;
    const int n4 = N_NODES * 64 / 4;
    if (i < n4)
        reinterpret_cast<float4*>(g_msum)[i] = make_float4(0.f, 0.f, 0.f, 0.f);
}

// ---------------------------------------------------------------------------
// Edge kernel: persistent, warp-specialized, HMMA tf32 (mma.sync m16n8k8).
//   warps 0-7 : consumers — each owns 16 edges x 64 cols
//   warps 8-15: producers — gather tile t+grid into the other A buffer
// ---------------------------------------------------------------------------
__global__ __launch_bounds__(THREADS, 1) void edge_kernel(
    const float* __restrict__ feat, const float* __restrict__ x,
    const int*   __restrict__ src,  const int*   __restrict__ dst,
    const float* __restrict__ W1,   const float* __restrict__ b1,
    const float* __restrict__ W2,   const float* __restrict__ b2,
    const float* __restrict__ we,   const float* __restrict__ be)
{
    extern __shared__ float sm[];
    const int tid = threadIdx.x;
    const int wid = tid >> 5;
    const int lane = tid & 31;

    // ---- init: zero A buffers (pad positions must stay 0) + W1 pad ----
    for (int i = tid * 4; i < 128 * SA_STR * 2; i += THREADS * 4)
        *reinterpret_cast<float4*>(sm + O_A0 + i) = make_float4(0.f, 0.f, 0.f, 0.f);
    for (int i = tid * 4; i < 64 * SW1_STR; i += THREADS * 4)
        *reinterpret_cast<float4*>(sm + O_W1 + i) = make_float4(0.f, 0.f, 0.f, 0.f);
    __syncthreads();

    // W1 input [129][64] (k-major) -> sW1[n][kpos(k)] as tf32 bits
    for (int i = tid; i < 129 * 64; i += THREADS) {
        int k = i >> 6, n = i & 63;
        reinterpret_cast<uint32_t*>(sm)[O_W1 + n * SW1_STR + kpos(k)] = tf32r(W1[i]);
    }
    // W2 input [64][64]
    for (int i = tid; i < 64 * 64; i += THREADS) {
        int k = i >> 6, n = i & 63;
        reinterpret_cast<uint32_t*>(sm)[O_W2 + n * SW2_STR + kpos(k)] = tf32r(W2[i]);
    }
    if (tid < 64) {
        sm[O_B1 + tid] = b1[tid];
        sm[O_B2 + tid] = b2[tid];
        sm[O_WE + tid] = we[tid];
    }
    if (tid == 0) sm[O_BE] = be[0];
    __syncthreads();

    // ---------------- producer lambda ----------------
    const int tp   = tid - 256;           // valid for wid>=8
    const int pe   = tp & 127;            // edge within tile
    const int part = tp >> 7;             // 0: src cols (k 0..63), 1: dst (64..127)

    auto fill = [&](float* A, int t) {
        const int idx = t * TILE_E + pe;
        const int nd  = part ? dst[idx] : src[idx];
        const float4* f = reinterpret_cast<const float4*>(feat + (size_t)nd * 64);
        uint32_t* row = reinterpret_cast<uint32_t*>(A + pe * SA_STR + part * 64);
        #pragma unroll
        for (int g8 = 0; g8 < 8; g8++) {
            float4 lo = f[2 * g8];
            float4 hi = f[2 * g8 + 1];
            *reinterpret_cast<uint4*>(row + g8 * 8) =
                make_uint4(tf32r(lo.x), tf32r(hi.x), tf32r(lo.y), tf32r(hi.y));
            *reinterpret_cast<uint4*>(row + g8 * 8 + 4) =
                make_uint4(tf32r(lo.z), tf32r(hi.z), tf32r(lo.w), tf32r(hi.w));
        }
        if (part) {
            const int s = src[idx];
            float dx = x[s * 3 + 0] - x[nd * 3 + 0];
            float dy = x[s * 3 + 1] - x[nd * 3 + 1];
            float dz = x[s * 3 + 2] - x[nd * 3 + 2];
            row[64] = tf32r(dx * dx + dy * dy + dz * dz);   // position 128
        }
    };

    // ---------------- consumer constants ----------------
    const int g  = lane >> 2;              // 0..7
    const int l4 = lane & 3;               // 0..3
    const int eb = wid * 16;               // edge base (consumers: wid 0..7)
    const int posA = (l4 < 2) ? 4 * l4 : 4 * l4 - 7;  // 0,4,1,5

    // ---- prologue: producers fill A0 with the first tile ----
    if (wid >= 8) fill(sm + O_A0, blockIdx.x);
    __syncthreads();

    int buf = 0;
    for (int t = blockIdx.x; t < N_TILES; t += NCTAS) {
        if (wid >= 8) {
            const int tn = t + NCTAS;
            if (tn < N_TILES) fill(sm + (buf ? O_A0 : O_A1), tn);
        } else {
            const float* A = sm + (buf ? O_A1 : O_A0);
            const uint32_t* Au  = reinterpret_cast<const uint32_t*>(A);
            const uint32_t* W1u = reinterpret_cast<const uint32_t*>(sm) + O_W1;
            const uint32_t* Hu  = reinterpret_cast<const uint32_t*>(sm) + O_H;
            const uint32_t* W2u = reinterpret_cast<const uint32_t*>(sm) + O_W2;

            // -------- layer 1: 17 k-steps --------
            float acc[8][4];
            #pragma unroll
            for (int ct = 0; ct < 8; ct++)
                acc[ct][0] = acc[ct][1] = acc[ct][2] = acc[ct][3] = 0.f;

            for (int kk = 0; kk < 17; kk++) {
                const int ko = kk * 8 + 2 * l4;
                uint2 alo = *reinterpret_cast<const uint2*>(Au + (eb + g) * SA_STR + ko);
                uint2 ahi = *reinterpret_cast<const uint2*>(Au + (eb + g + 8) * SA_STR + ko);
                #pragma unroll
                for (int ct = 0; ct < 8; ct++) {
                    uint2 bv = *reinterpret_cast<const uint2*>(
                        W1u + (ct * 8 + g) * SW1_STR + ko);
                    mma8(acc[ct], alo.x, ahi.x, alo.y, ahi.y, bv.x, bv.y);
                }
            }

            // -------- epilogue 1: h = relu(d1 + b1) -> H (own rows only) ----
            uint32_t* Hw = reinterpret_cast<uint32_t*>(sm) + O_H;
            #pragma unroll
            for (int ct = 0; ct < 8; ct++) {
                const int c0 = ct * 8 + 2 * l4;
                const float bb0 = sm[O_B1 + c0], bb1 = sm[O_B1 + c0 + 1];
                float h0 = fmaxf(acc[ct][0] + bb0, 0.f);
                float h1 = fmaxf(acc[ct][1] + bb1, 0.f);
                float h2 = fmaxf(acc[ct][2] + bb0, 0.f);
                float h3 = fmaxf(acc[ct][3] + bb1, 0.f);
                Hw[(eb + g) * SH_STR + ct * 8 + posA]         = tf32r(h0);
                Hw[(eb + g) * SH_STR + ct * 8 + posA + 2]     = tf32r(h1);
                Hw[(eb + g + 8) * SH_STR + ct * 8 + posA]     = tf32r(h2);
                Hw[(eb + g + 8) * SH_STR + ct * 8 + posA + 2] = tf32r(h3);
            }
            __syncwarp();

            // -------- layer 2: 8 k-steps --------
            #pragma unroll
            for (int ct = 0; ct < 8; ct++)
                acc[ct][0] = acc[ct][1] = acc[ct][2] = acc[ct][3] = 0.f;

            for (int kk = 0; kk < 8; kk++) {
                const int ko = kk * 8 + 2 * l4;
                uint2 alo = *reinterpret_cast<const uint2*>(Hu + (eb + g) * SH_STR + ko);
                uint2 ahi = *reinterpret_cast<const uint2*>(Hu + (eb + g + 8) * SH_STR + ko);
                #pragma unroll
                for (int ct = 0; ct < 8; ct++) {
                    uint2 bv = *reinterpret_cast<const uint2*>(
                        W2u + (ct * 8 + g) * SW2_STR + ko);
                    mma8(acc[ct], alo.x, ahi.x, alo.y, ahi.y, bv.x, bv.y);
                }
            }

            // -------- epilogue 2: m = relu(d2+b2), gate, scatter --------
            float m[8][4];
            float pg = 0.f, pg8 = 0.f;
            #pragma unroll
            for (int ct = 0; ct < 8; ct++) {
                const int c0 = ct * 8 + 2 * l4;
                const float bb0 = sm[O_B2 + c0], bb1 = sm[O_B2 + c0 + 1];
                const float w0 = sm[O_WE + c0],  w1 = sm[O_WE + c0 + 1];
                m[ct][0] = fmaxf(acc[ct][0] + bb0, 0.f);
                m[ct][1] = fmaxf(acc[ct][1] + bb1, 0.f);
                m[ct][2] = fmaxf(acc[ct][2] + bb0, 0.f);
                m[ct][3] = fmaxf(acc[ct][3] + bb1, 0.f);
                pg  = fmaf(m[ct][0], w0, fmaf(m[ct][1], w1, pg));
                pg8 = fmaf(m[ct][2], w0, fmaf(m[ct][3], w1, pg8));
            }
            // reduce across the 4 lanes of each row-quad
            pg  += __shfl_xor_sync(0xffffffffu, pg, 1);
            pg  += __shfl_xor_sync(0xffffffffu, pg, 2);
            pg8 += __shfl_xor_sync(0xffffffffu, pg8, 1);
            pg8 += __shfl_xor_sync(0xffffffffu, pg8, 2);
            const float be0 = sm[O_BE];
            const float G  = 1.f / (1.f + __expf(-(pg + be0)));
            const float G8 = 1.f / (1.f + __expf(-(pg8 + be0)));

            const int dg  = dst[t * TILE_E + eb + g];
            const int dg8 = dst[t * TILE_E + eb + g + 8];
            float* bp  = g_msum + (size_t)dg * 64;
            float* bp8 = g_msum + (size_t)dg8 * 64;
            #pragma unroll
            for (int ct = 0; ct < 8; ct++) {
                const int c0 = ct * 8 + 2 * l4;
                red2(bp + c0,  m[ct][0] * G,  m[ct][1] * G);
                red2(bp8 + c0, m[ct][2] * G8, m[ct][3] * G8);
            }
        }
        __syncthreads();
        buf ^= 1;
    }
}

// ---------------------------------------------------------------------------
// Node kernel: warp per node.
// ---------------------------------------------------------------------------
__global__ __launch_bounds__(256) void node_kernel(
    const float* __restrict__ feat,
    const float* __restrict__ U1, const float* __restrict__ c1,
    const float* __restrict__ U2, const float* __restrict__ c2,
    float* __restrict__ out)
{
    __shared__ float sU1[64 * 64];
    __shared__ float sU2[64 * 64];
    __shared__ float sc1[64];
    __shared__ float sc2[64];
    __shared__ float buf[8][128];

    const int tid = threadIdx.x;
    for (int i = tid; i < 64 * 64; i += 256) { sU1[i] = U1[i]; sU2[i] = U2[i]; }
    if (tid < 64) { sc1[tid] = c1[tid]; sc2[tid] = c2[tid]; }
    __syncthreads();

    const int w = tid >> 5;
    const int l = tid & 31;
    float* nbuf = buf[w];
    float* hb   = buf[w] + 64;

    const float2* u1v = reinterpret_cast<const float2*>(sU1);
    const float2* u2v = reinterpret_cast<const float2*>(sU2);
    const float c1a = sc1[2 * l], c1b = sc1[2 * l + 1];
    const float c2a = sc2[2 * l], c2b = sc2[2 * l + 1];

    for (int n = blockIdx.x * 8 + w; n < N_NODES; n += gridDim.x * 8) {
        const float2 f  = reinterpret_cast<const float2*>(feat + (size_t)n * 64)[l];
        const float2 ms = reinterpret_cast<const float2*>(g_msum + (size_t)n * 64)[l];
        reinterpret_cast<float2*>(nbuf)[l] = make_float2(ms.x + f.x, ms.y + f.y);
        __syncwarp();

        float a0 = c1a, a1 = c1b;
        #pragma unroll 4
        for (int k = 0; k < 64; k++) {
            float vk = nbuf[k];
            float2 uv = u1v[k * 32 + l];
            a0 = fmaf(vk, uv.x, a0);
            a1 = fmaf(vk, uv.y, a1);
        }
        a0 = fmaxf(a0, 0.f);
        a1 = fmaxf(a1, 0.f);
        reinterpret_cast<float2*>(hb)[l] = make_float2(a0, a1);
        __syncwarp();

        float o0 = c2a, o1 = c2b;
        #pragma unroll 4
        for (int k = 0; k < 64; k++) {
            float hk = hb[k];
            float2 uv = u2v[k * 32 + l];
            o0 = fmaf(hk, uv.x, o0);
            o1 = fmaf(hk, uv.y, o1);
        }
        reinterpret_cast<float2*>(out + (size_t)n * 64)[l] =
            make_float2(o0 + f.x, o1 + f.y);
        __syncwarp();
    }
}

// ---------------------------------------------------------------------------
extern "C" void kernel_launch(void* const* d_in, const int* in_sizes, int n_in,
                              void* d_out, int out_size)
{
    const float* feat = (const float*)d_in[0];
    const float* x    = (const float*)d_in[1];
    const int*   src  = (const int*)  d_in[2];
    const int*   dst  = (const int*)  d_in[3];
    const float* W1   = (const float*)d_in[4];
    const float* b1   = (const float*)d_in[5];
    const float* W2   = (const float*)d_in[6];
    const float* b2   = (const float*)d_in[7];
    const float* we   = (const float*)d_in[8];
    const float* be   = (const float*)d_in[9];
    const float* U1   = (const float*)d_in[10];
    const float* c1   = (const float*)d_in[11];
    const float* U2   = (const float*)d_in[12];
    const float* c2   = (const float*)d_in[13];
    float* out = (float*)d_out;

    cudaFuncSetAttribute(edge_kernel,
                         cudaFuncAttributeMaxDynamicSharedMemorySize,
                         SMEM_BYTES);

    {
        const int n4 = N_NODES * 64 / 4;
        zero_msum_kernel<<<(n4 + 255) / 256, 256>>>();
    }
    edge_kernel<<<NCTAS, THREADS, SMEM_BYTES>>>(feat, x, src, dst,
                                                W1, b1, W2, b2, we, be);
    node_kernel<<<1184, 256>>>(feat, U1, c1, U2, c2, out);
}

// round 6
// speedup vs baseline: 4.7070x; 1.3209x over previous
#include <cuda_runtime.h>
#include <math.h>
#include <cstdint>

#define N_NODES 50000
#define N_EDGES 800000
#define TILE_E  128
#define N_TILES (N_EDGES / TILE_E)   // 6250
#define THREADS 512
#define NCTAS   152

// A-tile stride (floats): 64 cols + 4 pad, ≡4 mod 32
#define SA_STR  68
#define SW2_STR 68

// smem word offsets (edge kernel)
#define O_A0   0
#define O_A1   (O_A0 + 128 * SA_STR)          // 8704
#define O_W2   (O_A1 + 128 * SA_STR)          // 17408
#define O_WL   (O_W2 + 64 * SW2_STR)          // 21760
#define O_B2   (O_WL + 64)
#define O_WE   (O_B2 + 64)
#define O_BE   (O_WE + 64)
#define SMEM_WORDS (O_BE + 8)
#define SMEM_BYTES (SMEM_WORDS * 4)           // ~87.9 KB

// Device scratch (no allocs allowed).
__device__ float g_msum[N_NODES * 64];
__device__ float g_P[N_NODES * 64];     // feat @ W1[0:64]  + b1
__device__ float g_Q[N_NODES * 64];     // feat @ W1[64:128]
__device__ float g_sqd[N_EDGES];        // per-edge squared distance

// k-permutation within each 8-group (HMMA tf32 fragment order)
__host__ __device__ __forceinline__ int kpos(int k) {
    return (k & ~7) + 2 * (k & 3) + ((k >> 2) & 1);
}
__device__ __forceinline__ uint32_t tf32r(float f) {
    uint32_t r; asm("cvt.rna.tf32.f32 %0, %1;" : "=r"(r) : "f"(f)); return r;
}
__device__ __forceinline__ void mma8(float d[4], uint32_t a0, uint32_t a1,
                                     uint32_t a2, uint32_t a3,
                                     uint32_t b0, uint32_t b1) {
    asm("mma.sync.aligned.m16n8k8.row.col.f32.tf32.tf32.f32 "
        "{%0,%1,%2,%3}, {%4,%5,%6,%7}, {%8,%9}, {%0,%1,%2,%3};"
        : "+f"(d[0]), "+f"(d[1]), "+f"(d[2]), "+f"(d[3])
        : "r"(a0), "r"(a1), "r"(a2), "r"(a3), "r"(b0), "r"(b1));
}
__device__ __forceinline__ void red2(float* p, float a, float b) {
    asm volatile("red.global.add.v2.f32 [%0], {%1,%2};"
                 :: "l"(p), "f"(a), "f"(b) : "memory");
}

// ---------------------------------------------------------------------------
// Prologue kernel: zero g_msum, per-edge sqd, per-node P/Q (layer-1 hoist).
// ---------------------------------------------------------------------------
__global__ __launch_bounds__(256) void pre_kernel(
    const float* __restrict__ feat, const float* __restrict__ x,
    const int*   __restrict__ src,  const int*   __restrict__ dst,
    const float* __restrict__ W1,   const float* __restrict__ b1)
{
    __shared__ float sW1a[64 * 64];
    __shared__ float sW1b[64 * 64];
    __shared__ float sb1[64];
    __shared__ float nb[8][64];

    const int tid = threadIdx.x;
    for (int i = tid; i < 64 * 64; i += 256) {
        sW1a[i] = W1[i];              // rows 0..63
        sW1b[i] = W1[4096 + i];       // rows 64..127
    }
    if (tid < 64) sb1[tid] = b1[tid];

    const int gid = blockIdx.x * 256 + tid;
    const int gstride = gridDim.x * 256;

    // zero the scatter accumulator
    for (int i = gid; i < N_NODES * 64 / 4; i += gstride)
        reinterpret_cast<float4*>(g_msum)[i] = make_float4(0.f, 0.f, 0.f, 0.f);

    // per-edge squared distance
    for (int e = gid; e < N_EDGES; e += gstride) {
        const int s = src[e], d = dst[e];
        float dx = x[3 * s + 0] - x[3 * d + 0];
        float dy = x[3 * s + 1] - x[3 * d + 1];
        float dz = x[3 * s + 2] - x[3 * d + 2];
        g_sqd[e] = dx * dx + dy * dy + dz * dz;
    }
    __syncthreads();

    // P/Q: warp per node
    const int w = tid >> 5;
    const int l = tid & 31;
    const float2* wav = reinterpret_cast<const float2*>(sW1a);
    const float2* wbv = reinterpret_cast<const float2*>(sW1b);
    const float ba = sb1[2 * l], bb = sb1[2 * l + 1];

    for (int n = blockIdx.x * 8 + w; n < N_NODES; n += gridDim.x * 8) {
        reinterpret_cast<float2*>(nb[w])[l] =
            reinterpret_cast<const float2*>(feat + (size_t)n * 64)[l];
        __syncwarp();
        float pa = ba, pb = bb, qa = 0.f, qb = 0.f;
        #pragma unroll 4
        for (int k = 0; k < 64; k++) {
            float f = nb[w][k];
            float2 va = wav[k * 32 + l];
            float2 vb = wbv[k * 32 + l];
            pa = fmaf(f, va.x, pa); pb = fmaf(f, va.y, pb);
            qa = fmaf(f, vb.x, qa); qb = fmaf(f, vb.y, qb);
        }
        reinterpret_cast<float2*>(g_P + (size_t)n * 64)[l] = make_float2(pa, pb);
        reinterpret_cast<float2*>(g_Q + (size_t)n * 64)[l] = make_float2(qa, qb);
        __syncwarp();
    }
}

// ---------------------------------------------------------------------------
// Edge kernel: persistent, warp-specialized.
//   warps 0-7 : consumers — layer-2 HMMA (tf32) + gate + scatter
//   warps 8-15: producers — h1 = relu(P[src]+Q[dst]+sqd*wl), warp per edge
// ---------------------------------------------------------------------------
__global__ __launch_bounds__(THREADS, 1) void edge_kernel(
    const int* __restrict__ src, const int* __restrict__ dst,
    const float* __restrict__ W1, const float* __restrict__ W2,
    const float* __restrict__ b2, const float* __restrict__ we,
    const float* __restrict__ be)
{
    extern __shared__ float sm[];
    const int tid = threadIdx.x;
    const int wid = tid >> 5;
    const int lane = tid & 31;

    // W2 [64][64] k-major -> sW2[n][kpos(k)] tf32
    for (int i = tid; i < 64 * 64; i += THREADS) {
        int k = i >> 6, n = i & 63;
        reinterpret_cast<uint32_t*>(sm)[O_W2 + n * SW2_STR + kpos(k)] = tf32r(W2[i]);
    }
    if (tid < 64) {
        sm[O_WL + tid] = W1[128 * 64 + tid];   // last row of W1
        sm[O_B2 + tid] = b2[tid];
        sm[O_WE + tid] = we[tid];
    }
    if (tid == 0) sm[O_BE] = be[0];
    __syncthreads();

    // ---------------- producer ----------------
    const int pw = wid - 8;                       // 0..7 for producers
    const int kp0 = kpos(lane);                   // col 'lane' position
    auto fill = [&](float* A, int t) {
        #pragma unroll 4
        for (int it = 0; it < 16; it++) {
            const int pe  = pw * 16 + it;
            const int idx = t * TILE_E + pe;
            const int s = src[idx];
            const int d = dst[idx];
            const float sq = g_sqd[idx];
            const float pA = g_P[(size_t)s * 64 + lane];
            const float pB = g_P[(size_t)s * 64 + 32 + lane];
            const float qA = g_Q[(size_t)d * 64 + lane];
            const float qB = g_Q[(size_t)d * 64 + 32 + lane];
            float h0 = fmaxf(pA + qA + sq * sm[O_WL + lane], 0.f);
            float h1 = fmaxf(pB + qB + sq * sm[O_WL + 32 + lane], 0.f);
            uint32_t* row = reinterpret_cast<uint32_t*>(A + pe * SA_STR);
            row[kp0]      = tf32r(h0);
            row[kp0 + 32] = tf32r(h1);
        }
    };

    // ---------------- consumer constants ----------------
    const int g  = lane >> 2;
    const int l4 = lane & 3;
    const int eb = wid * 16;

    // prologue: fill A0 with the first tile
    if (wid >= 8) fill(sm + O_A0, blockIdx.x);
    __syncthreads();

    int buf = 0;
    for (int t = blockIdx.x; t < N_TILES; t += NCTAS) {
        if (wid >= 8) {
            const int tn = t + NCTAS;
            if (tn < N_TILES) fill(sm + (buf ? O_A0 : O_A1), tn);
        } else {
            const uint32_t* Au =
                reinterpret_cast<const uint32_t*>(sm + (buf ? O_A1 : O_A0));
            const uint32_t* W2u = reinterpret_cast<const uint32_t*>(sm) + O_W2;

            // -------- layer 2: 8 k-steps, 64 HMMA --------
            float acc[8][4];
            #pragma unroll
            for (int ct = 0; ct < 8; ct++)
                acc[ct][0] = acc[ct][1] = acc[ct][2] = acc[ct][3] = 0.f;

            #pragma unroll
            for (int kk = 0; kk < 8; kk++) {
                const int ko = kk * 8 + 2 * l4;
                uint2 alo = *reinterpret_cast<const uint2*>(Au + (eb + g) * SA_STR + ko);
                uint2 ahi = *reinterpret_cast<const uint2*>(Au + (eb + g + 8) * SA_STR + ko);
                #pragma unroll
                for (int ct = 0; ct < 8; ct++) {
                    uint2 bv = *reinterpret_cast<const uint2*>(
                        W2u + (ct * 8 + g) * SW2_STR + ko);
                    mma8(acc[ct], alo.x, ahi.x, alo.y, ahi.y, bv.x, bv.y);
                }
            }

            // -------- epilogue: m = relu(d2+b2), gate, scatter --------
            float m[8][4];
            float pg = 0.f, pg8 = 0.f;
            #pragma unroll
            for (int ct = 0; ct < 8; ct++) {
                const int c0 = ct * 8 + 2 * l4;
                const float bb0 = sm[O_B2 + c0], bb1 = sm[O_B2 + c0 + 1];
                const float w0 = sm[O_WE + c0],  w1 = sm[O_WE + c0 + 1];
                m[ct][0] = fmaxf(acc[ct][0] + bb0, 0.f);
                m[ct][1] = fmaxf(acc[ct][1] + bb1, 0.f);
                m[ct][2] = fmaxf(acc[ct][2] + bb0, 0.f);
                m[ct][3] = fmaxf(acc[ct][3] + bb1, 0.f);
                pg  = fmaf(m[ct][0], w0, fmaf(m[ct][1], w1, pg));
                pg8 = fmaf(m[ct][2], w0, fmaf(m[ct][3], w1, pg8));
            }
            pg  += __shfl_xor_sync(0xffffffffu, pg, 1);
            pg  += __shfl_xor_sync(0xffffffffu, pg, 2);
            pg8 += __shfl_xor_sync(0xffffffffu, pg8, 1);
            pg8 += __shfl_xor_sync(0xffffffffu, pg8, 2);
            const float be0 = sm[O_BE];
            const float G  = 1.f / (1.f + __expf(-(pg + be0)));
            const float G8 = 1.f / (1.f + __expf(-(pg8 + be0)));

            const int dg  = dst[t * TILE_E + eb + g];
            const int dg8 = dst[t * TILE_E + eb + g + 8];
            float* bp  = g_msum + (size_t)dg * 64;
            float* bp8 = g_msum + (size_t)dg8 * 64;
            #pragma unroll
            for (int ct = 0; ct < 8; ct++) {
                const int c0 = ct * 8 + 2 * l4;
                red2(bp + c0,  m[ct][0] * G,  m[ct][1] * G);
                red2(bp8 + c0, m[ct][2] * G8, m[ct][3] * G8);
            }
        }
        __syncthreads();
        buf ^= 1;
    }
}

// ---------------------------------------------------------------------------
// Node kernel: warp per node (unchanged).
// ---------------------------------------------------------------------------
__global__ __launch_bounds__(256) void node_kernel(
    const float* __restrict__ feat,
    const float* __restrict__ U1, const float* __restrict__ c1,
    const float* __restrict__ U2, const float* __restrict__ c2,
    float* __restrict__ out)
{
    __shared__ float sU1[64 * 64];
    __shared__ float sU2[64 * 64];
    __shared__ float sc1[64];
    __shared__ float sc2[64];
    __shared__ float buf[8][128];

    const int tid = threadIdx.x;
    for (int i = tid; i < 64 * 64; i += 256) { sU1[i] = U1[i]; sU2[i] = U2[i]; }
    if (tid < 64) { sc1[tid] = c1[tid]; sc2[tid] = c2[tid]; }
    __syncthreads();

    const int w = tid >> 5;
    const int l = tid & 31;
    float* nbuf = buf[w];
    float* hb   = buf[w] + 64;

    const float2* u1v = reinterpret_cast<const float2*>(sU1);
    const float2* u2v = reinterpret_cast<const float2*>(sU2);
    const float c1a = sc1[2 * l], c1b = sc1[2 * l + 1];
    const float c2a = sc2[2 * l], c2b = sc2[2 * l + 1];

    for (int n = blockIdx.x * 8 + w; n < N_NODES; n += gridDim.x * 8) {
        const float2 f  = reinterpret_cast<const float2*>(feat + (size_t)n * 64)[l];
        const float2 ms = reinterpret_cast<const float2*>(g_msum + (size_t)n * 64)[l];
        reinterpret_cast<float2*>(nbuf)[l] = make_float2(ms.x + f.x, ms.y + f.y);
        __syncwarp();

        float a0 = c1a, a1 = c1b;
        #pragma unroll 4
        for (int k = 0; k < 64; k++) {
            float vk = nbuf[k];
            float2 uv = u1v[k * 32 + l];
            a0 = fmaf(vk, uv.x, a0);
            a1 = fmaf(vk, uv.y, a1);
        }
        a0 = fmaxf(a0, 0.f);
        a1 = fmaxf(a1, 0.f);
        reinterpret_cast<float2*>(hb)[l] = make_float2(a0, a1);
        __syncwarp();

        float o0 = c2a, o1 = c2b;
        #pragma unroll 4
        for (int k = 0; k < 64; k++) {
            float hk = hb[k];
            float2 uv = u2v[k * 32 + l];
            o0 = fmaf(hk, uv.x, o0);
            o1 = fmaf(hk, uv.y, o1);
        }
        reinterpret_cast<float2*>(out + (size_t)n * 64)[l] =
            make_float2(o0 + f.x, o1 + f.y);
        __syncwarp();
    }
}

// ---------------------------------------------------------------------------
extern "C" void kernel_launch(void* const* d_in, const int* in_sizes, int n_in,
                              void* d_out, int out_size)
{
    const float* feat = (const float*)d_in[0];
    const float* x    = (const float*)d_in[1];
    const int*   src  = (const int*)  d_in[2];
    const int*   dst  = (const int*)  d_in[3];
    const float* W1   = (const float*)d_in[4];
    const float* b1   = (const float*)d_in[5];
    const float* W2   = (const float*)d_in[6];
    const float* b2   = (const float*)d_in[7];
    const float* we   = (const float*)d_in[8];
    const float* be   = (const float*)d_in[9];
    const float* U1   = (const float*)d_in[10];
    const float* c1   = (const float*)d_in[11];
    const float* U2   = (const float*)d_in[12];
    const float* c2   = (const float*)d_in[13];
    float* out = (float*)d_out;

    cudaFuncSetAttribute(edge_kernel,
                         cudaFuncAttributeMaxDynamicSharedMemorySize,
                         SMEM_BYTES);

    pre_kernel<<<1184, 256>>>(feat, x, src, dst, W1, b1);
    edge_kernel<<<NCTAS, THREADS, SMEM_BYTES>>>(src, dst, W1, W2, b2, we, be);
    node_kernel<<<1184, 256>>>(feat, U1, c1, U2, c2, out);
}

// round 8
// speedup vs baseline: 7.8224x; 1.6618x over previous
#include <cuda_runtime.h>
#include <cuda_fp16.h>
#include <math.h>
#include <cstdint>

#define N_NODES 50000
#define N_EDGES 800000
#define TILE_E  128
#define N_TILES (N_EDGES / TILE_E)   // 6250
#define THREADS 512
#define NCTAS   152
#define NGRP    (N_NODES / 16)       // 3125 exact

// Device scratch (no allocs allowed).
__device__ float g_msum[N_NODES * 64];
__device__ float g_P[N_NODES * 64];     // feat @ W1[0:64]  + b1
__device__ float g_Q[N_NODES * 64];     // feat @ W1[64:128]
__device__ float g_sqd[N_EDGES];        // per-edge squared distance

// fragment permutation within each 8-slot group (works for tf32 k-slots and
// f16 32-bit word-slots alike): slot s -> pos (s&~7) + 2*(s&3) + ((s>>2)&1)
__host__ __device__ __forceinline__ int kpos(int s) {
    return (s & ~7) + 2 * (s & 3) + ((s >> 2) & 1);
}
__device__ __forceinline__ uint32_t tf32r(float f) {
    uint32_t r; asm("cvt.rna.tf32.f32 %0, %1;" : "=r"(r) : "f"(f)); return r;
}
__device__ __forceinline__ void mma8(float d[4], uint32_t a0, uint32_t a1,
                                     uint32_t a2, uint32_t a3,
                                     uint32_t b0, uint32_t b1) {
    asm("mma.sync.aligned.m16n8k8.row.col.f32.tf32.tf32.f32 "
        "{%0,%1,%2,%3}, {%4,%5,%6,%7}, {%8,%9}, {%0,%1,%2,%3};"
        : "+f"(d[0]), "+f"(d[1]), "+f"(d[2]), "+f"(d[3])
        : "r"(a0), "r"(a1), "r"(a2), "r"(a3), "r"(b0), "r"(b1));
}
__device__ __forceinline__ void mma16h(float d[4], uint32_t a0, uint32_t a1,
                                       uint32_t a2, uint32_t a3,
                                       uint32_t b0, uint32_t b1) {
    asm("mma.sync.aligned.m16n8k16.row.col.f32.f16.f16.f32 "
        "{%0,%1,%2,%3}, {%4,%5,%6,%7}, {%8,%9}, {%0,%1,%2,%3};"
        : "+f"(d[0]), "+f"(d[1]), "+f"(d[2]), "+f"(d[3])
        : "r"(a0), "r"(a1), "r"(a2), "r"(a3), "r"(b0), "r"(b1));
}
__device__ __forceinline__ void red4(float* p, float a, float b, float c, float d) {
    asm volatile("red.global.add.v4.f32 [%0], {%1,%2,%3,%4};"
                 :: "l"(p), "f"(a), "f"(b), "f"(c), "f"(d) : "memory");
}

// ---------------------------------------------------------------------------
// pre_kernel: zero g_msum, per-edge sqd, and PQ = feat @ [W1a|W1b] via
// HMMA tf32 (warp-independent 16-row groups).
// smem (floats): sW [128][68] = 8704 | sb1 64 | per-warp A [16][68] x 8 = 8704
// ---------------------------------------------------------------------------
#define PRE_SMEM_WORDS (8704 + 64 + 8 * 1088)
#define PRE_SMEM_BYTES (PRE_SMEM_WORDS * 4)    // 69,888

__global__ __launch_bounds__(256) void pre_kernel(
    const float* __restrict__ feat, const float* __restrict__ x,
    const int*   __restrict__ src,  const int*   __restrict__ dst,
    const float* __restrict__ W1,   const float* __restrict__ b1)
{
    extern __shared__ float ps[];
    float* sW  = ps;
    float* sb1 = ps + 8704;
    const int tid = threadIdx.x;
    const int w   = tid >> 5;
    const int l   = tid & 31;
    const int g   = l >> 2;
    const int l4  = l & 3;
    uint32_t* pA = reinterpret_cast<uint32_t*>(ps + 8768 + w * 1088);

    // weights: B[n][k], n in [0,128): n<64 -> W1a col n, else W1b col n-64
    for (int i = tid; i < 128 * 64; i += 256) {
        int n = i >> 6, k = i & 63;
        float v = (n < 64) ? W1[k * 64 + n] : W1[(64 + k) * 64 + (n - 64)];
        reinterpret_cast<uint32_t*>(sW)[n * 68 + kpos(k)] = tf32r(v);
    }
    if (tid < 64) sb1[tid] = b1[tid];

    // zero scatter accumulator + per-edge sqd (grid-stride)
    const int gid = blockIdx.x * 256 + tid;
    const int gs  = gridDim.x * 256;
    for (int i = gid; i < N_NODES * 16; i += gs)
        reinterpret_cast<float4*>(g_msum)[i] = make_float4(0.f, 0.f, 0.f, 0.f);
    for (int e = gid; e < N_EDGES; e += gs) {
        const int s = src[e], d = dst[e];
        float dx = x[3 * s + 0] - x[3 * d + 0];
        float dy = x[3 * s + 1] - x[3 * d + 1];
        float dz = x[3 * s + 2] - x[3 * d + 2];
        g_sqd[e] = dx * dx + dy * dy + dz * dz;
    }
    __syncthreads();

    for (int grp = blockIdx.x * 8 + w; grp < NGRP; grp += gridDim.x * 8) {
        const int n0 = grp * 16;
        // stage 16 feat rows as tf32 (k-permuted)
        #pragma unroll 4
        for (int r = 0; r < 16; r++) {
            float2 f = *reinterpret_cast<const float2*>(
                feat + (size_t)(n0 + r) * 64 + 2 * l);
            uint32_t* row = pA + r * 68;
            row[kpos(2 * l)]     = tf32r(f.x);
            row[kpos(2 * l + 1)] = tf32r(f.y);
        }
        __syncwarp();

        float acc[16][4];
        #pragma unroll
        for (int ct = 0; ct < 16; ct++)
            acc[ct][0] = acc[ct][1] = acc[ct][2] = acc[ct][3] = 0.f;

        #pragma unroll
        for (int kk = 0; kk < 8; kk++) {
            const int ko = kk * 8 + 2 * l4;
            uint2 alo = *reinterpret_cast<const uint2*>(pA + g * 68 + ko);
            uint2 ahi = *reinterpret_cast<const uint2*>(pA + (g + 8) * 68 + ko);
            #pragma unroll
            for (int ct = 0; ct < 16; ct++) {
                uint2 bv = *reinterpret_cast<const uint2*>(
                    reinterpret_cast<uint32_t*>(sW) + (ct * 8 + g) * 68 + ko);
                mma8(acc[ct], alo.x, ahi.x, alo.y, ahi.y, bv.x, bv.y);
            }
        }

        #pragma unroll
        for (int ct = 0; ct < 16; ct++) {
            const int n = ct * 8 + 2 * l4;
            if (ct < 8) {
                const float bb0 = sb1[n], bb1 = sb1[n + 1];
                *reinterpret_cast<float2*>(g_P + (size_t)(n0 + g) * 64 + n) =
                    make_float2(acc[ct][0] + bb0, acc[ct][1] + bb1);
                *reinterpret_cast<float2*>(g_P + (size_t)(n0 + g + 8) * 64 + n) =
                    make_float2(acc[ct][2] + bb0, acc[ct][3] + bb1);
            } else {
                const int nq = n - 64;
                *reinterpret_cast<float2*>(g_Q + (size_t)(n0 + g) * 64 + nq) =
                    make_float2(acc[ct][0], acc[ct][1]);
                *reinterpret_cast<float2*>(g_Q + (size_t)(n0 + g + 8) * 64 + nq) =
                    make_float2(acc[ct][2], acc[ct][3]);
            }
        }
        __syncwarp();
    }
}

// ---------------------------------------------------------------------------
// Edge kernel: persistent, warp-specialized.
//   warps 0-7 : consumers — layer-2 HMMA fp16 (m16n8k16) + gate + red4 scatter
//   warps 8-15: producers — h1 = relu(P[src]+Q[dst]+sqd*wl) packed to half2
// smem words: A0 [128][36]=4608 | A1 4608 | W2f [64][36]=2304 | misc
// ---------------------------------------------------------------------------
#define O_A0   0
#define O_A1   4608
#define O_W2F  9216
#define O_WL   11520
#define O_B2   11584
#define O_WE   11648
#define O_BE   11712
#define EDGE_SMEM_WORDS 11720   // 46,880 B (static)

__global__ __launch_bounds__(THREADS, 1) void edge_kernel(
    const int* __restrict__ src, const int* __restrict__ dst,
    const float* __restrict__ W1, const float* __restrict__ W2,
    const float* __restrict__ b2, const float* __restrict__ we,
    const float* __restrict__ be)
{
    __shared__ float sm[EDGE_SMEM_WORDS];
    const int tid  = threadIdx.x;
    const int wid  = tid >> 5;
    const int lane = tid & 31;

    // W2 [k][n] -> f16 B layout [n][word kpos(k>>1)], halves (k even, k odd)
    for (int i = tid; i < 64 * 64; i += THREADS) {
        int k = i >> 6, n = i & 63;
        __half* rowp = reinterpret_cast<__half*>(
            reinterpret_cast<uint32_t*>(sm) + O_W2F + n * 36);
        rowp[kpos(k >> 1) * 2 + (k & 1)] = __float2half(W2[i]);
    }
    if (tid < 64) {
        sm[O_WL + tid] = W1[128 * 64 + tid];
        sm[O_B2 + tid] = b2[tid];
        sm[O_WE + tid] = we[tid];
    }
    if (tid == 0) sm[O_BE] = be[0];
    __syncthreads();

    // ---------------- producer ----------------
    const int pw    = wid - 8;
    const int kposl = kpos(lane);
    auto fill = [&](uint32_t* A, int t) {
        const float2 wl = *reinterpret_cast<const float2*>(sm + O_WL + 2 * lane);
        #pragma unroll 4
        for (int it = 0; it < 16; it++) {
            const int pe  = pw * 16 + it;
            const int idx = t * TILE_E + pe;
            const int s = src[idx];
            const int d = dst[idx];
            const float sq = g_sqd[idx];
            float2 p2 = *reinterpret_cast<const float2*>(g_P + (size_t)s * 64 + 2 * lane);
            float2 q2 = *reinterpret_cast<const float2*>(g_Q + (size_t)d * 64 + 2 * lane);
            float h0 = fmaxf(p2.x + q2.x + sq * wl.x, 0.f);
            float h1 = fmaxf(p2.y + q2.y + sq * wl.y, 0.f);
            __half2 hv = __floats2half2_rn(h0, h1);
            A[pe * 36 + kposl] = *reinterpret_cast<uint32_t*>(&hv);
        }
    };

    // ---------------- consumer constants ----------------
    const int g  = lane >> 2;
    const int l4 = lane & 3;
    const int eb = wid * 16;
    const bool evenlane = !(l4 & 1);

    if (wid >= 8) fill(reinterpret_cast<uint32_t*>(sm) + O_A0, blockIdx.x);
    __syncthreads();

    int buf = 0;
    for (int t = blockIdx.x; t < N_TILES; t += NCTAS) {
        if (wid >= 8) {
            const int tn = t + NCTAS;
            if (tn < N_TILES)
                fill(reinterpret_cast<uint32_t*>(sm) + (buf ? O_A0 : O_A1), tn);
        } else {
            const uint32_t* Au =
                reinterpret_cast<const uint32_t*>(sm) + (buf ? O_A1 : O_A0);
            const uint32_t* W2u = reinterpret_cast<const uint32_t*>(sm) + O_W2F;

            // -------- layer 2: 4 k16-steps, 32 HMMA --------
            float acc[8][4];
            #pragma unroll
            for (int ct = 0; ct < 8; ct++)
                acc[ct][0] = acc[ct][1] = acc[ct][2] = acc[ct][3] = 0.f;

            #pragma unroll
            for (int kk = 0; kk < 4; kk++) {
                const int ko = kk * 8 + 2 * l4;
                uint2 alo = *reinterpret_cast<const uint2*>(Au + (eb + g) * 36 + ko);
                uint2 ahi = *reinterpret_cast<const uint2*>(Au + (eb + g + 8) * 36 + ko);
                #pragma unroll
                for (int ct = 0; ct < 8; ct++) {
                    uint2 bv = *reinterpret_cast<const uint2*>(
                        W2u + (ct * 8 + g) * 36 + ko);
                    mma16h(acc[ct], alo.x, ahi.x, alo.y, ahi.y, bv.x, bv.y);
                }
            }

            // -------- epilogue: m = relu(d2+b2), gate --------
            float m[8][4];
            float pg = 0.f, pg8 = 0.f;
            #pragma unroll
            for (int ct = 0; ct < 8; ct++) {
                const int c0 = ct * 8 + 2 * l4;
                const float bb0 = sm[O_B2 + c0], bb1 = sm[O_B2 + c0 + 1];
                const float w0 = sm[O_WE + c0],  w1 = sm[O_WE + c0 + 1];
                m[ct][0] = fmaxf(acc[ct][0] + bb0, 0.f);
                m[ct][1] = fmaxf(acc[ct][1] + bb1, 0.f);
                m[ct][2] = fmaxf(acc[ct][2] + bb0, 0.f);
                m[ct][3] = fmaxf(acc[ct][3] + bb1, 0.f);
                pg  = fmaf(m[ct][0], w0, fmaf(m[ct][1], w1, pg));
                pg8 = fmaf(m[ct][2], w0, fmaf(m[ct][3], w1, pg8));
            }
            pg  += __shfl_xor_sync(0xffffffffu, pg, 1);
            pg  += __shfl_xor_sync(0xffffffffu, pg, 2);
            pg8 += __shfl_xor_sync(0xffffffffu, pg8, 1);
            pg8 += __shfl_xor_sync(0xffffffffu, pg8, 2);
            const float be0 = sm[O_BE];
            const float G  = 1.f / (1.f + __expf(-(pg + be0)));
            const float G8 = 1.f / (1.f + __expf(-(pg8 + be0)));

            // -------- scatter: lane pairs -> red.v4 from even lanes --------
            const int dg  = dst[t * TILE_E + eb + g];
            const int dg8 = dst[t * TILE_E + eb + g + 8];
            float* bp  = g_msum + (size_t)dg * 64;
            float* bp8 = g_msum + (size_t)dg8 * 64;
            #pragma unroll
            for (int ct = 0; ct < 8; ct++) {
                const int c0 = ct * 8 + 2 * l4;
                float v0 = m[ct][0] * G,  v1 = m[ct][1] * G;
                float v2 = m[ct][2] * G8, v3 = m[ct][3] * G8;
                float o0 = __shfl_xor_sync(0xffffffffu, v0, 1);
                float o1 = __shfl_xor_sync(0xffffffffu, v1, 1);
                float o2 = __shfl_xor_sync(0xffffffffu, v2, 1);
                float o3 = __shfl_xor_sync(0xffffffffu, v3, 1);
                if (evenlane) {
                    red4(bp + c0,  v0, v1, o0, o1);
                    red4(bp8 + c0, v2, v3, o2, o3);
                }
            }
        }
        __syncthreads();
        buf ^= 1;
    }
}

// ---------------------------------------------------------------------------
// node_kernel: HMMA tf32, warp-independent 16-row groups.
//   out = relu((msum+feat)@U1 + c1) @ U2 + c2 + feat
// smem words: sU1 4352 | sU2 4352 | c1 64 | c2 64 | per-warp (A+H) 2176 x 8
// ---------------------------------------------------------------------------
#define NODE_SMEM_WORDS (4352 + 4352 + 64 + 64 + 8 * 2176)
#define NODE_SMEM_BYTES (NODE_SMEM_WORDS * 4)   // 104,960

__global__ __launch_bounds__(256) void node_kernel(
    const float* __restrict__ feat,
    const float* __restrict__ U1, const float* __restrict__ c1,
    const float* __restrict__ U2, const float* __restrict__ c2,
    float* __restrict__ out)
{
    extern __shared__ float ns[];
    float* sU1 = ns;
    float* sU2 = ns + 4352;
    float* sc1 = ns + 8704;
    float* sc2 = ns + 8768;
    const int tid = threadIdx.x;
    const int w   = tid >> 5;
    const int l   = tid & 31;
    const int g   = l >> 2;
    const int l4  = l & 3;
    uint32_t* pA = reinterpret_cast<uint32_t*>(ns + 8832 + w * 2176);
    uint32_t* pH = pA + 1088;

    for (int i = tid; i < 64 * 64; i += 256) {
        int k = i >> 6, n = i & 63;
        reinterpret_cast<uint32_t*>(sU1)[n * 68 + kpos(k)] = tf32r(U1[i]);
        reinterpret_cast<uint32_t*>(sU2)[n * 68 + kpos(k)] = tf32r(U2[i]);
    }
    if (tid < 64) { sc1[tid] = c1[tid]; sc2[tid] = c2[tid]; }
    __syncthreads();

    for (int grp = blockIdx.x * 8 + w; grp < NGRP; grp += gridDim.x * 8) {
        const int n0 = grp * 16;
        // stage A = msum + feat (tf32, k-permuted)
        #pragma unroll 4
        for (int r = 0; r < 16; r++) {
            float2 ms = *reinterpret_cast<const float2*>(
                g_msum + (size_t)(n0 + r) * 64 + 2 * l);
            float2 f = *reinterpret_cast<const float2*>(
                feat + (size_t)(n0 + r) * 64 + 2 * l);
            uint32_t* row = pA + r * 68;
            row[kpos(2 * l)]     = tf32r(ms.x + f.x);
            row[kpos(2 * l + 1)] = tf32r(ms.y + f.y);
        }
        __syncwarp();

        // layer 1
        float acc[8][4];
        #pragma unroll
        for (int ct = 0; ct < 8; ct++)
            acc[ct][0] = acc[ct][1] = acc[ct][2] = acc[ct][3] = 0.f;
        #pragma unroll
        for (int kk = 0; kk < 8; kk++) {
            const int ko = kk * 8 + 2 * l4;
            uint2 alo = *reinterpret_cast<const uint2*>(pA + g * 68 + ko);
            uint2 ahi = *reinterpret_cast<const uint2*>(pA + (g + 8) * 68 + ko);
            #pragma unroll
            for (int ct = 0; ct < 8; ct++) {
                uint2 bv = *reinterpret_cast<const uint2*>(
                    reinterpret_cast<uint32_t*>(sU1) + (ct * 8 + g) * 68 + ko);
                mma8(acc[ct], alo.x, ahi.x, alo.y, ahi.y, bv.x, bv.y);
            }
        }
        // epilogue 1: relu -> H (own rows)
        #pragma unroll
        for (int ct = 0; ct < 8; ct++) {
            const int c0 = ct * 8 + 2 * l4;
            const float bb0 = sc1[c0], bb1 = sc1[c0 + 1];
            pH[g * 68 + kpos(c0)]           = tf32r(fmaxf(acc[ct][0] + bb0, 0.f));
            pH[g * 68 + kpos(c0 + 1)]       = tf32r(fmaxf(acc[ct][1] + bb1, 0.f));
            pH[(g + 8) * 68 + kpos(c0)]     = tf32r(fmaxf(acc[ct][2] + bb0, 0.f));
            pH[(g + 8) * 68 + kpos(c0 + 1)] = tf32r(fmaxf(acc[ct][3] + bb1, 0.f));
        }
        __syncwarp();

        // layer 2
        #pragma unroll
        for (int ct = 0; ct < 8; ct++)
            acc[ct][0] = acc[ct][1] = acc[ct][2] = acc[ct][3] = 0.f;
        #pragma unroll
        for (int kk = 0; kk < 8; kk++) {
            const int ko = kk * 8 + 2 * l4;
            uint2 alo = *reinterpret_cast<const uint2*>(pH + g * 68 + ko);
            uint2 ahi = *reinterpret_cast<const uint2*>(pH + (g + 8) * 68 + ko);
            #pragma unroll
            for (int ct = 0; ct < 8; ct++) {
                uint2 bv = *reinterpret_cast<const uint2*>(
                    reinterpret_cast<uint32_t*>(sU2) + (ct * 8 + g) * 68 + ko);
                mma8(acc[ct], alo.x, ahi.x, alo.y, ahi.y, bv.x, bv.y);
            }
        }
        // epilogue 2: + c2 + feat residual
        #pragma unroll
        for (int ct = 0; ct < 8; ct++) {
            const int c0 = ct * 8 + 2 * l4;
            const float bb0 = sc2[c0], bb1 = sc2[c0 + 1];
            float2 f0 = *reinterpret_cast<const float2*>(
                feat + (size_t)(n0 + g) * 64 + c0);
            float2 f1 = *reinterpret_cast<const float2*>(
                feat + (size_t)(n0 + g + 8) * 64 + c0);
            *reinterpret_cast<float2*>(out + (size_t)(n0 + g) * 64 + c0) =
                make_float2(acc[ct][0] + bb0 + f0.x, acc[ct][1] + bb1 + f0.y);
            *reinterpret_cast<float2*>(out + (size_t)(n0 + g + 8) * 64 + c0) =
                make_float2(acc[ct][2] + bb0 + f1.x, acc[ct][3] + bb1 + f1.y);
        }
        __syncwarp();
    }
}

// ---------------------------------------------------------------------------
extern "C" void kernel_launch(void* const* d_in, const int* in_sizes, int n_in,
                              void* d_out, int out_size)
{
    const float* feat = (const float*)d_in[0];
    const float* x    = (const float*)d_in[1];
    const int*   src  = (const int*)  d_in[2];
    const int*   dst  = (const int*)  d_in[3];
    const float* W1   = (const float*)d_in[4];
    const float* b1   = (const float*)d_in[5];
    const float* W2   = (const float*)d_in[6];
    const float* b2   = (const float*)d_in[7];
    const float* we   = (const float*)d_in[8];
    const float* be   = (const float*)d_in[9];
    const float* U1   = (const float*)d_in[10];
    const float* c1   = (const float*)d_in[11];
    const float* U2   = (const float*)d_in[12];
    const float* c2   = (const float*)d_in[13];
    float* out = (float*)d_out;

    cudaFuncSetAttribute(pre_kernel,
                         cudaFuncAttributeMaxDynamicSharedMemorySize,
                         PRE_SMEM_BYTES);
    cudaFuncSetAttribute(node_kernel,
                         cudaFuncAttributeMaxDynamicSharedMemorySize,
                         NODE_SMEM_BYTES);

    pre_kernel<<<391, 256, PRE_SMEM_BYTES>>>(feat, x, src, dst, W1, b1);
    edge_kernel<<<NCTAS, THREADS>>>(src, dst, W1, W2, b2, we, be);
    node_kernel<<<391, 256, NODE_SMEM_BYTES>>>(feat, U1, c1, U2, c2, out);
}

// round 9
// speedup vs baseline: 8.5302x; 1.0905x over previous
#include <cuda_runtime.h>
#include <cuda_fp16.h>
#include <math.h>
#include <cstdint>

#define N_NODES 50000
#define N_EDGES 800000
#define TILE_E  128
#define N_TILES (N_EDGES / TILE_E)   // 6250
#define THREADS 512
#define NCTAS   152
#define NGRP    (N_NODES / 16)       // 3125 exact

// Device scratch (no allocs allowed).
__device__ float g_msum[N_NODES * 64];
__device__ float g_P[N_NODES * 64];     // feat @ W1[0:64]  + b1
__device__ float g_Q[N_NODES * 64];     // feat @ W1[64:128]
__device__ float g_sqd[N_EDGES];        // per-edge squared distance

// fragment permutation within each 8-slot group (tf32 k-slots / f16 word-slots)
__host__ __device__ __forceinline__ int kpos(int s) {
    return (s & ~7) + 2 * (s & 3) + ((s >> 2) & 1);
}
__device__ __forceinline__ uint32_t tf32r(float f) {
    uint32_t r; asm("cvt.rna.tf32.f32 %0, %1;" : "=r"(r) : "f"(f)); return r;
}
__device__ __forceinline__ void mma8(float d[4], uint32_t a0, uint32_t a1,
                                     uint32_t a2, uint32_t a3,
                                     uint32_t b0, uint32_t b1) {
    asm("mma.sync.aligned.m16n8k8.row.col.f32.tf32.tf32.f32 "
        "{%0,%1,%2,%3}, {%4,%5,%6,%7}, {%8,%9}, {%0,%1,%2,%3};"
        : "+f"(d[0]), "+f"(d[1]), "+f"(d[2]), "+f"(d[3])
        : "r"(a0), "r"(a1), "r"(a2), "r"(a3), "r"(b0), "r"(b1));
}
__device__ __forceinline__ void mma16h(float d[4], uint32_t a0, uint32_t a1,
                                       uint32_t a2, uint32_t a3,
                                       uint32_t b0, uint32_t b1) {
    asm("mma.sync.aligned.m16n8k16.row.col.f32.f16.f16.f32 "
        "{%0,%1,%2,%3}, {%4,%5,%6,%7}, {%8,%9}, {%0,%1,%2,%3};"
        : "+f"(d[0]), "+f"(d[1]), "+f"(d[2]), "+f"(d[3])
        : "r"(a0), "r"(a1), "r"(a2), "r"(a3), "r"(b0), "r"(b1));
}
__device__ __forceinline__ void red4(float* p, float a, float b, float c, float d) {
    asm volatile("red.global.add.v4.f32 [%0], {%1,%2,%3,%4};"
                 :: "l"(p), "f"(a), "f"(b), "f"(c), "f"(d) : "memory");
}

// ---------------------------------------------------------------------------
// zs_kernel: zero g_msum + per-edge squared distance (memory-bound, big grid)
// ---------------------------------------------------------------------------
__global__ __launch_bounds__(256) void zs_kernel(
    const float* __restrict__ x,
    const int* __restrict__ src, const int* __restrict__ dst)
{
    const int gid = blockIdx.x * 256 + threadIdx.x;
    const int gs  = gridDim.x * 256;
    for (int i = gid; i < N_NODES * 16; i += gs)
        reinterpret_cast<float4*>(g_msum)[i] = make_float4(0.f, 0.f, 0.f, 0.f);
    for (int e = gid; e < N_EDGES; e += gs) {
        const int s = src[e], d = dst[e];
        float dx = x[3 * s + 0] - x[3 * d + 0];
        float dy = x[3 * s + 1] - x[3 * d + 1];
        float dz = x[3 * s + 2] - x[3 * d + 2];
        g_sqd[e] = dx * dx + dy * dy + dz * dz;
    }
}

// ---------------------------------------------------------------------------
// pq_kernel: PQ = feat @ [W1a|W1b] via HMMA tf32, two passes over the B
// halves to keep registers low (acc[8][4]).
// smem (floats): sW [128][68] = 8704 | sb1 64 | per-warp A [16][68] x 8
// ---------------------------------------------------------------------------
#define PQ_SMEM_WORDS (8704 + 64 + 8 * 1088)
#define PQ_SMEM_BYTES (PQ_SMEM_WORDS * 4)    // 69,888

__global__ __launch_bounds__(256) void pq_kernel(
    const float* __restrict__ feat,
    const float* __restrict__ W1, const float* __restrict__ b1)
{
    extern __shared__ float ps[];
    float* sW  = ps;
    float* sb1 = ps + 8704;
    const int tid = threadIdx.x;
    const int w   = tid >> 5;
    const int l   = tid & 31;
    const int g   = l >> 2;
    const int l4  = l & 3;
    uint32_t* pA = reinterpret_cast<uint32_t*>(ps + 8768 + w * 1088);

    // B[n][k]: n<64 -> W1a col n (-> P), n>=64 -> W1b col n-64 (-> Q)
    for (int i = tid; i < 128 * 64; i += 256) {
        int n = i >> 6, k = i & 63;
        float v = (n < 64) ? W1[k * 64 + n] : W1[(64 + k) * 64 + (n - 64)];
        reinterpret_cast<uint32_t*>(sW)[n * 68 + kpos(k)] = tf32r(v);
    }
    if (tid < 64) sb1[tid] = b1[tid];
    __syncthreads();

    for (int grp = blockIdx.x * 8 + w; grp < NGRP; grp += gridDim.x * 8) {
        const int n0 = grp * 16;
        #pragma unroll 4
        for (int r = 0; r < 16; r++) {
            float2 f = *reinterpret_cast<const float2*>(
                feat + (size_t)(n0 + r) * 64 + 2 * l);
            uint32_t* row = pA + r * 68;
            row[kpos(2 * l)]     = tf32r(f.x);
            row[kpos(2 * l + 1)] = tf32r(f.y);
        }
        __syncwarp();

        #pragma unroll
        for (int pass = 0; pass < 2; pass++) {
            float acc[8][4];
            #pragma unroll
            for (int ct = 0; ct < 8; ct++)
                acc[ct][0] = acc[ct][1] = acc[ct][2] = acc[ct][3] = 0.f;

            #pragma unroll
            for (int kk = 0; kk < 8; kk++) {
                const int ko = kk * 8 + 2 * l4;
                uint2 alo = *reinterpret_cast<const uint2*>(pA + g * 68 + ko);
                uint2 ahi = *reinterpret_cast<const uint2*>(pA + (g + 8) * 68 + ko);
                #pragma unroll
                for (int ct = 0; ct < 8; ct++) {
                    uint2 bv = *reinterpret_cast<const uint2*>(
                        reinterpret_cast<uint32_t*>(sW) +
                        ((pass * 8 + ct) * 8 + g) * 68 + ko);
                    mma8(acc[ct], alo.x, ahi.x, alo.y, ahi.y, bv.x, bv.y);
                }
            }

            float* dstbuf = pass ? g_Q : g_P;
            #pragma unroll
            for (int ct = 0; ct < 8; ct++) {
                const int n = ct * 8 + 2 * l4;
                const float bb0 = pass ? 0.f : sb1[n];
                const float bb1 = pass ? 0.f : sb1[n + 1];
                *reinterpret_cast<float2*>(dstbuf + (size_t)(n0 + g) * 64 + n) =
                    make_float2(acc[ct][0] + bb0, acc[ct][1] + bb1);
                *reinterpret_cast<float2*>(dstbuf + (size_t)(n0 + g + 8) * 64 + n) =
                    make_float2(acc[ct][2] + bb0, acc[ct][3] + bb1);
            }
        }
        __syncwarp();
    }
}

// ---------------------------------------------------------------------------
// Edge kernel: persistent, warp-specialized.
//   warps 0-7 : consumers — layer-2 HMMA fp16 (m16n8k16) + gate + red4 scatter
//   warps 8-15: producers — h1 = relu(P[src]+Q[dst]+sqd*wl), software-pipelined
// smem words: A0 [128][36]=4608 | A1 4608 | W2f [64][36]=2304 | misc
// ---------------------------------------------------------------------------
#define O_A0   0
#define O_A1   4608
#define O_W2F  9216
#define O_WL   11520
#define O_B2   11584
#define O_WE   11648
#define O_BE   11712
#define EDGE_SMEM_WORDS 11720   // 46,880 B (static)

__global__ __launch_bounds__(THREADS, 1) void edge_kernel(
    const int* __restrict__ src, const int* __restrict__ dst,
    const float* __restrict__ W1, const float* __restrict__ W2,
    const float* __restrict__ b2, const float* __restrict__ we,
    const float* __restrict__ be)
{
    __shared__ float sm[EDGE_SMEM_WORDS];
    const int tid  = threadIdx.x;
    const int wid  = tid >> 5;
    const int lane = tid & 31;

    // W2 [k][n] -> f16 B layout [n][word kpos(k>>1)], halves (k even, k odd)
    for (int i = tid; i < 64 * 64; i += THREADS) {
        int k = i >> 6, n = i & 63;
        __half* rowp = reinterpret_cast<__half*>(
            reinterpret_cast<uint32_t*>(sm) + O_W2F + n * 36);
        rowp[kpos(k >> 1) * 2 + (k & 1)] = __float2half(W2[i]);
    }
    if (tid < 64) {
        sm[O_WL + tid] = W1[128 * 64 + tid];
        sm[O_B2 + tid] = b2[tid];
        sm[O_WE + tid] = we[tid];
    }
    if (tid == 0) sm[O_BE] = be[0];
    __syncthreads();

    // ---------------- producer (software-pipelined) ----------------
    const int pw    = wid - 8;
    const int kposl = kpos(lane);
    auto fill = [&](uint32_t* A, int t) {
        const float2 wl = *reinterpret_cast<const float2*>(sm + O_WL + 2 * lane);
        const int e0 = t * TILE_E + pw * 16;
        int   sI = 0, dI = 0;
        float sqI = 0.f;
        if (lane < 16) {
            sI  = src[e0 + lane];
            dI  = dst[e0 + lane];
            sqI = g_sqd[e0 + lane];
        }
        #pragma unroll
        for (int b = 0; b < 2; b++) {
            float2 pv[8], qv[8];
            #pragma unroll
            for (int j = 0; j < 8; j++) {
                const int it = b * 8 + j;
                const int s = __shfl_sync(0xffffffffu, sI, it);
                const int d = __shfl_sync(0xffffffffu, dI, it);
                pv[j] = *reinterpret_cast<const float2*>(g_P + (size_t)s * 64 + 2 * lane);
                qv[j] = *reinterpret_cast<const float2*>(g_Q + (size_t)d * 64 + 2 * lane);
            }
            #pragma unroll
            for (int j = 0; j < 8; j++) {
                const int it = b * 8 + j;
                const float sq = __shfl_sync(0xffffffffu, sqI, it);
                float h0 = fmaxf(pv[j].x + qv[j].x + sq * wl.x, 0.f);
                float h1 = fmaxf(pv[j].y + qv[j].y + sq * wl.y, 0.f);
                __half2 hv = __floats2half2_rn(h0, h1);
                A[(pw * 16 + it) * 36 + kposl] = *reinterpret_cast<uint32_t*>(&hv);
            }
        }
    };

    // ---------------- consumer constants ----------------
    const int g  = lane >> 2;
    const int l4 = lane & 3;
    const int eb = wid * 16;
    const bool evenlane = !(l4 & 1);

    if (wid >= 8) fill(reinterpret_cast<uint32_t*>(sm) + O_A0, blockIdx.x);
    __syncthreads();

    int buf = 0;
    for (int t = blockIdx.x; t < N_TILES; t += NCTAS) {
        if (wid >= 8) {
            const int tn = t + NCTAS;
            if (tn < N_TILES)
                fill(reinterpret_cast<uint32_t*>(sm) + (buf ? O_A0 : O_A1), tn);
        } else {
            const uint32_t* Au =
                reinterpret_cast<const uint32_t*>(sm) + (buf ? O_A1 : O_A0);
            const uint32_t* W2u = reinterpret_cast<const uint32_t*>(sm) + O_W2F;

            // -------- layer 2: 4 k16-steps, 32 HMMA --------
            float acc[8][4];
            #pragma unroll
            for (int ct = 0; ct < 8; ct++)
                acc[ct][0] = acc[ct][1] = acc[ct][2] = acc[ct][3] = 0.f;

            #pragma unroll
            for (int kk = 0; kk < 4; kk++) {
                const int ko = kk * 8 + 2 * l4;
                uint2 alo = *reinterpret_cast<const uint2*>(Au + (eb + g) * 36 + ko);
                uint2 ahi = *reinterpret_cast<const uint2*>(Au + (eb + g + 8) * 36 + ko);
                #pragma unroll
                for (int ct = 0; ct < 8; ct++) {
                    uint2 bv = *reinterpret_cast<const uint2*>(
                        W2u + (ct * 8 + g) * 36 + ko);
                    mma16h(acc[ct], alo.x, ahi.x, alo.y, ahi.y, bv.x, bv.y);
                }
            }

            // -------- epilogue: m = relu(d2+b2), gate --------
            float m[8][4];
            float pg = 0.f, pg8 = 0.f;
            #pragma unroll
            for (int ct = 0; ct < 8; ct++) {
                const int c0 = ct * 8 + 2 * l4;
                const float bb0 = sm[O_B2 + c0], bb1 = sm[O_B2 + c0 + 1];
                const float w0 = sm[O_WE + c0],  w1 = sm[O_WE + c0 + 1];
                m[ct][0] = fmaxf(acc[ct][0] + bb0, 0.f);
                m[ct][1] = fmaxf(acc[ct][1] + bb1, 0.f);
                m[ct][2] = fmaxf(acc[ct][2] + bb0, 0.f);
                m[ct][3] = fmaxf(acc[ct][3] + bb1, 0.f);
                pg  = fmaf(m[ct][0], w0, fmaf(m[ct][1], w1, pg));
                pg8 = fmaf(m[ct][2], w0, fmaf(m[ct][3], w1, pg8));
            }
            pg  += __shfl_xor_sync(0xffffffffu, pg, 1);
            pg  += __shfl_xor_sync(0xffffffffu, pg, 2);
            pg8 += __shfl_xor_sync(0xffffffffu, pg8, 1);
            pg8 += __shfl_xor_sync(0xffffffffu, pg8, 2);
            const float be0 = sm[O_BE];
            const float G  = 1.f / (1.f + __expf(-(pg + be0)));
            const float G8 = 1.f / (1.f + __expf(-(pg8 + be0)));

            // -------- scatter: lane pairs -> red.v4 from even lanes --------
            const int dg  = dst[t * TILE_E + eb + g];
            const int dg8 = dst[t * TILE_E + eb + g + 8];
            float* bp  = g_msum + (size_t)dg * 64;
            float* bp8 = g_msum + (size_t)dg8 * 64;
            #pragma unroll
            for (int ct = 0; ct < 8; ct++) {
                const int c0 = ct * 8 + 2 * l4;
                float v0 = m[ct][0] * G,  v1 = m[ct][1] * G;
                float v2 = m[ct][2] * G8, v3 = m[ct][3] * G8;
                float o0 = __shfl_xor_sync(0xffffffffu, v0, 1);
                float o1 = __shfl_xor_sync(0xffffffffu, v1, 1);
                float o2 = __shfl_xor_sync(0xffffffffu, v2, 1);
                float o3 = __shfl_xor_sync(0xffffffffu, v3, 1);
                if (evenlane) {
                    red4(bp + c0,  v0, v1, o0, o1);
                    red4(bp8 + c0, v2, v3, o2, o3);
                }
            }
        }
        __syncthreads();
        buf ^= 1;
    }
}

// ---------------------------------------------------------------------------
// node_kernel: HMMA tf32, warp-independent 16-row groups.
//   out = relu((msum+feat)@U1 + c1) @ U2 + c2 + feat
// ---------------------------------------------------------------------------
#define NODE_SMEM_WORDS (4352 + 4352 + 64 + 64 + 8 * 2176)
#define NODE_SMEM_BYTES (NODE_SMEM_WORDS * 4)   // 104,960

__global__ __launch_bounds__(256) void node_kernel(
    const float* __restrict__ feat,
    const float* __restrict__ U1, const float* __restrict__ c1,
    const float* __restrict__ U2, const float* __restrict__ c2,
    float* __restrict__ out)
{
    extern __shared__ float ns[];
    float* sU1 = ns;
    float* sU2 = ns + 4352;
    float* sc1 = ns + 8704;
    float* sc2 = ns + 8768;
    const int tid = threadIdx.x;
    const int w   = tid >> 5;
    const int l   = tid & 31;
    const int g   = l >> 2;
    const int l4  = l & 3;
    uint32_t* pA = reinterpret_cast<uint32_t*>(ns + 8832 + w * 2176);
    uint32_t* pH = pA + 1088;

    for (int i = tid; i < 64 * 64; i += 256) {
        int k = i >> 6, n = i & 63;
        reinterpret_cast<uint32_t*>(sU1)[n * 68 + kpos(k)] = tf32r(U1[i]);
        reinterpret_cast<uint32_t*>(sU2)[n * 68 + kpos(k)] = tf32r(U2[i]);
    }
    if (tid < 64) { sc1[tid] = c1[tid]; sc2[tid] = c2[tid]; }
    __syncthreads();

    for (int grp = blockIdx.x * 8 + w; grp < NGRP; grp += gridDim.x * 8) {
        const int n0 = grp * 16;
        #pragma unroll 4
        for (int r = 0; r < 16; r++) {
            float2 ms = *reinterpret_cast<const float2*>(
                g_msum + (size_t)(n0 + r) * 64 + 2 * l);
            float2 f = *reinterpret_cast<const float2*>(
                feat + (size_t)(n0 + r) * 64 + 2 * l);
            uint32_t* row = pA + r * 68;
            row[kpos(2 * l)]     = tf32r(ms.x + f.x);
            row[kpos(2 * l + 1)] = tf32r(ms.y + f.y);
        }
        __syncwarp();

        // layer 1
        float acc[8][4];
        #pragma unroll
        for (int ct = 0; ct < 8; ct++)
            acc[ct][0] = acc[ct][1] = acc[ct][2] = acc[ct][3] = 0.f;
        #pragma unroll
        for (int kk = 0; kk < 8; kk++) {
            const int ko = kk * 8 + 2 * l4;
            uint2 alo = *reinterpret_cast<const uint2*>(pA + g * 68 + ko);
            uint2 ahi = *reinterpret_cast<const uint2*>(pA + (g + 8) * 68 + ko);
            #pragma unroll
            for (int ct = 0; ct < 8; ct++) {
                uint2 bv = *reinterpret_cast<const uint2*>(
                    reinterpret_cast<uint32_t*>(sU1) + (ct * 8 + g) * 68 + ko);
                mma8(acc[ct], alo.x, ahi.x, alo.y, ahi.y, bv.x, bv.y);
            }
        }
        // epilogue 1: relu -> H (own rows)
        #pragma unroll
        for (int ct = 0; ct < 8; ct++) {
            const int c0 = ct * 8 + 2 * l4;
            const float bb0 = sc1[c0], bb1 = sc1[c0 + 1];
            pH[g * 68 + kpos(c0)]           = tf32r(fmaxf(acc[ct][0] + bb0, 0.f));
            pH[g * 68 + kpos(c0 + 1)]       = tf32r(fmaxf(acc[ct][1] + bb1, 0.f));
            pH[(g + 8) * 68 + kpos(c0)]     = tf32r(fmaxf(acc[ct][2] + bb0, 0.f));
            pH[(g + 8) * 68 + kpos(c0 + 1)] = tf32r(fmaxf(acc[ct][3] + bb1, 0.f));
        }
        __syncwarp();

        // layer 2
        #pragma unroll
        for (int ct = 0; ct < 8; ct++)
            acc[ct][0] = acc[ct][1] = acc[ct][2] = acc[ct][3] = 0.f;
        #pragma unroll
        for (int kk = 0; kk < 8; kk++) {
            const int ko = kk * 8 + 2 * l4;
            uint2 alo = *reinterpret_cast<const uint2*>(pH + g * 68 + ko);
            uint2 ahi = *reinterpret_cast<const uint2*>(pH + (g + 8) * 68 + ko);
            #pragma unroll
            for (int ct = 0; ct < 8; ct++) {
                uint2 bv = *reinterpret_cast<const uint2*>(
                    reinterpret_cast<uint32_t*>(sU2) + (ct * 8 + g) * 68 + ko);
                mma8(acc[ct], alo.x, ahi.x, alo.y, ahi.y, bv.x, bv.y);
            }
        }
        // epilogue 2: + c2 + feat residual
        #pragma unroll
        for (int ct = 0; ct < 8; ct++) {
            const int c0 = ct * 8 + 2 * l4;
            const float bb0 = sc2[c0], bb1 = sc2[c0 + 1];
            float2 f0 = *reinterpret_cast<const float2*>(
                feat + (size_t)(n0 + g) * 64 + c0);
            float2 f1 = *reinterpret_cast<const float2*>(
                feat + (size_t)(n0 + g + 8) * 64 + c0);
            *reinterpret_cast<float2*>(out + (size_t)(n0 + g) * 64 + c0) =
                make_float2(acc[ct][0] + bb0 + f0.x, acc[ct][1] + bb1 + f0.y);
            *reinterpret_cast<float2*>(out + (size_t)(n0 + g + 8) * 64 + c0) =
                make_float2(acc[ct][2] + bb0 + f1.x, acc[ct][3] + bb1 + f1.y);
        }
        __syncwarp();
    }
}

// ---------------------------------------------------------------------------
extern "C" void kernel_launch(void* const* d_in, const int* in_sizes, int n_in,
                              void* d_out, int out_size)
{
    const float* feat = (const float*)d_in[0];
    const float* x    = (const float*)d_in[1];
    const int*   src  = (const int*)  d_in[2];
    const int*   dst  = (const int*)  d_in[3];
    const float* W1   = (const float*)d_in[4];
    const float* b1   = (const float*)d_in[5];
    const float* W2   = (const float*)d_in[6];
    const float* b2   = (const float*)d_in[7];
    const float* we   = (const float*)d_in[8];
    const float* be   = (const float*)d_in[9];
    const float* U1   = (const float*)d_in[10];
    const float* c1   = (const float*)d_in[11];
    const float* U2   = (const float*)d_in[12];
    const float* c2   = (const float*)d_in[13];
    float* out = (float*)d_out;

    cudaFuncSetAttribute(pq_kernel,
                         cudaFuncAttributeMaxDynamicSharedMemorySize,
                         PQ_SMEM_BYTES);
    cudaFuncSetAttribute(node_kernel,
                         cudaFuncAttributeMaxDynamicSharedMemorySize,
                         NODE_SMEM_BYTES);

    zs_kernel<<<1184, 256>>>(x, src, dst);
    pq_kernel<<<391, 256, PQ_SMEM_BYTES>>>(feat, W1, b1);
    edge_kernel<<<NCTAS, THREADS>>>(src, dst, W1, W2, b2, we, be);
    node_kernel<<<391, 256, NODE_SMEM_BYTES>>>(feat, U1, c1, U2, c2, out);
}

// round 10
// speedup vs baseline: 9.7575x; 1.1439x over previous
#include <cuda_runtime.h>
#include <cuda_fp16.h>
#include <math.h>
#include <cstdint>

#define N_NODES 50000
#define N_EDGES 800000
#define TILE_E  64
#define N_TILES (N_EDGES / TILE_E)   // 12500
#define NCTAS   456                  // 3 per SM
#define NGRP    (N_NODES / 16)       // 3125 exact

// Device scratch (no allocs allowed).
__device__ float g_msum[N_NODES * 64];
__device__ float g_P[N_NODES * 64];     // feat @ W1[0:64]  + b1
__device__ float g_Q[N_NODES * 64];     // feat @ W1[64:128]
__device__ float g_sqd[N_EDGES];        // per-edge squared distance

// fragment permutation within each 8-slot group (tf32 k-slots / f16 word-slots)
__host__ __device__ __forceinline__ int kpos(int s) {
    return (s & ~7) + 2 * (s & 3) + ((s >> 2) & 1);
}
__device__ __forceinline__ uint32_t tf32r(float f) {
    uint32_t r; asm("cvt.rna.tf32.f32 %0, %1;" : "=r"(r) : "f"(f)); return r;
}
__device__ __forceinline__ void mma8(float d[4], uint32_t a0, uint32_t a1,
                                     uint32_t a2, uint32_t a3,
                                     uint32_t b0, uint32_t b1) {
    asm("mma.sync.aligned.m16n8k8.row.col.f32.tf32.tf32.f32 "
        "{%0,%1,%2,%3}, {%4,%5,%6,%7}, {%8,%9}, {%0,%1,%2,%3};"
        : "+f"(d[0]), "+f"(d[1]), "+f"(d[2]), "+f"(d[3])
        : "r"(a0), "r"(a1), "r"(a2), "r"(a3), "r"(b0), "r"(b1));
}
__device__ __forceinline__ void mma16h(float d[4], uint32_t a0, uint32_t a1,
                                       uint32_t a2, uint32_t a3,
                                       uint32_t b0, uint32_t b1) {
    asm("mma.sync.aligned.m16n8k16.row.col.f32.f16.f16.f32 "
        "{%0,%1,%2,%3}, {%4,%5,%6,%7}, {%8,%9}, {%0,%1,%2,%3};"
        : "+f"(d[0]), "+f"(d[1]), "+f"(d[2]), "+f"(d[3])
        : "r"(a0), "r"(a1), "r"(a2), "r"(a3), "r"(b0), "r"(b1));
}
__device__ __forceinline__ void red4(float* p, float a, float b, float c, float d) {
    asm volatile("red.global.add.v4.f32 [%0], {%1,%2,%3,%4};"
                 :: "l"(p), "f"(a), "f"(b), "f"(c), "f"(d) : "memory");
}

// ---------------------------------------------------------------------------
// zs_kernel: zero g_msum + per-edge squared distance
// ---------------------------------------------------------------------------
__global__ __launch_bounds__(256) void zs_kernel(
    const float* __restrict__ x,
    const int* __restrict__ src, const int* __restrict__ dst)
{
    const int gid = blockIdx.x * 256 + threadIdx.x;
    const int gs  = gridDim.x * 256;
    for (int i = gid; i < N_NODES * 16; i += gs)
        reinterpret_cast<float4*>(g_msum)[i] = make_float4(0.f, 0.f, 0.f, 0.f);
    for (int e = gid; e < N_EDGES; e += gs) {
        const int s = src[e], d = dst[e];
        float dx = x[3 * s + 0] - x[3 * d + 0];
        float dy = x[3 * s + 1] - x[3 * d + 1];
        float dz = x[3 * s + 2] - x[3 * d + 2];
        g_sqd[e] = dx * dx + dy * dy + dz * dz;
    }
}

// ---------------------------------------------------------------------------
// pq_kernel: PQ = feat @ [W1a|W1b] via HMMA tf32, two B-half passes.
// smem (floats): sW [128][68] = 8704 | sb1 64 | per-warp A [16][68] x 8
// ---------------------------------------------------------------------------
#define PQ_SMEM_WORDS (8704 + 64 + 8 * 1088)
#define PQ_SMEM_BYTES (PQ_SMEM_WORDS * 4)    // 69,888

__global__ __launch_bounds__(256, 3) void pq_kernel(
    const float* __restrict__ feat,
    const float* __restrict__ W1, const float* __restrict__ b1)
{
    extern __shared__ float ps[];
    float* sW  = ps;
    float* sb1 = ps + 8704;
    const int tid = threadIdx.x;
    const int w   = tid >> 5;
    const int l   = tid & 31;
    const int g   = l >> 2;
    const int l4  = l & 3;
    uint32_t* pA = reinterpret_cast<uint32_t*>(ps + 8768 + w * 1088);

    for (int i = tid; i < 128 * 64; i += 256) {
        int n = i >> 6, k = i & 63;
        float v = (n < 64) ? W1[k * 64 + n] : W1[(64 + k) * 64 + (n - 64)];
        reinterpret_cast<uint32_t*>(sW)[n * 68 + kpos(k)] = tf32r(v);
    }
    if (tid < 64) sb1[tid] = b1[tid];
    __syncthreads();

    for (int grp = blockIdx.x * 8 + w; grp < NGRP; grp += gridDim.x * 8) {
        const int n0 = grp * 16;
        #pragma unroll 4
        for (int r = 0; r < 16; r++) {
            float2 f = *reinterpret_cast<const float2*>(
                feat + (size_t)(n0 + r) * 64 + 2 * l);
            uint32_t* row = pA + r * 68;
            row[kpos(2 * l)]     = tf32r(f.x);
            row[kpos(2 * l + 1)] = tf32r(f.y);
        }
        __syncwarp();

        #pragma unroll
        for (int pass = 0; pass < 2; pass++) {
            float acc[8][4];
            #pragma unroll
            for (int ct = 0; ct < 8; ct++)
                acc[ct][0] = acc[ct][1] = acc[ct][2] = acc[ct][3] = 0.f;

            #pragma unroll
            for (int kk = 0; kk < 8; kk++) {
                const int ko = kk * 8 + 2 * l4;
                uint2 alo = *reinterpret_cast<const uint2*>(pA + g * 68 + ko);
                uint2 ahi = *reinterpret_cast<const uint2*>(pA + (g + 8) * 68 + ko);
                #pragma unroll
                for (int ct = 0; ct < 8; ct++) {
                    uint2 bv = *reinterpret_cast<const uint2*>(
                        reinterpret_cast<uint32_t*>(sW) +
                        ((pass * 8 + ct) * 8 + g) * 68 + ko);
                    mma8(acc[ct], alo.x, ahi.x, alo.y, ahi.y, bv.x, bv.y);
                }
            }

            float* dstbuf = pass ? g_Q : g_P;
            #pragma unroll
            for (int ct = 0; ct < 8; ct++) {
                const int n = ct * 8 + 2 * l4;
                const float bb0 = pass ? 0.f : sb1[n];
                const float bb1 = pass ? 0.f : sb1[n + 1];
                *reinterpret_cast<float2*>(dstbuf + (size_t)(n0 + g) * 64 + n) =
                    make_float2(acc[ct][0] + bb0, acc[ct][1] + bb1);
                *reinterpret_cast<float2*>(dstbuf + (size_t)(n0 + g + 8) * 64 + n) =
                    make_float2(acc[ct][2] + bb0, acc[ct][3] + bb1);
            }
        }
        __syncwarp();
    }
}

// ---------------------------------------------------------------------------
// Edge kernel: persistent, 3 CTAs/SM, 64-edge tiles.
//   warps 0-3: consumers — layer-2 HMMA fp16 + gate + full-width red4 scatter
//   warps 4-7: producers — h1 = relu(P[src]+Q[dst]+sqd*wl), pipelined
// smem words: A0 [64][36]=2304 | A1 2304 | W2f [64][36]=2304 | misc
// ---------------------------------------------------------------------------
#define O_A0   0
#define O_A1   2304
#define O_W2F  4608
#define O_WL   6912
#define O_B2   6976
#define O_WE   7040
#define O_BE   7104
#define EDGE_SMEM_WORDS 7112   // 28,448 B static

__global__ __launch_bounds__(256, 3) void edge_kernel(
    const int* __restrict__ src, const int* __restrict__ dst,
    const float* __restrict__ W1, const float* __restrict__ W2,
    const float* __restrict__ b2, const float* __restrict__ we,
    const float* __restrict__ be)
{
    __shared__ float sm[EDGE_SMEM_WORDS];
    const int tid  = threadIdx.x;
    const int wid  = tid >> 5;
    const int lane = tid & 31;

    // W2 [k][n] -> f16 B layout [n][word kpos(k>>1)], halves (k even, k odd)
    for (int i = tid; i < 64 * 64; i += 256) {
        int k = i >> 6, n = i & 63;
        __half* rowp = reinterpret_cast<__half*>(
            reinterpret_cast<uint32_t*>(sm) + O_W2F + n * 36);
        rowp[kpos(k >> 1) * 2 + (k & 1)] = __float2half(W2[i]);
    }
    if (tid < 64) {
        sm[O_WL + tid] = W1[128 * 64 + tid];
        sm[O_B2 + tid] = b2[tid];
        sm[O_WE + tid] = we[tid];
    }
    if (tid == 0) sm[O_BE] = be[0];
    __syncthreads();

    // ---------------- producer (software-pipelined) ----------------
    const int pw    = wid - 4;
    const int kposl = kpos(lane);
    auto fill = [&](uint32_t* A, int t) {
        const float2 wl = *reinterpret_cast<const float2*>(sm + O_WL + 2 * lane);
        const int e0 = t * TILE_E + pw * 16;
        int   sI = 0, dI = 0;
        float sqI = 0.f;
        if (lane < 16) {
            sI  = src[e0 + lane];
            dI  = dst[e0 + lane];
            sqI = g_sqd[e0 + lane];
        }
        #pragma unroll
        for (int b = 0; b < 2; b++) {
            float2 pv[8], qv[8];
            #pragma unroll
            for (int j = 0; j < 8; j++) {
                const int it = b * 8 + j;
                const int s = __shfl_sync(0xffffffffu, sI, it);
                const int d = __shfl_sync(0xffffffffu, dI, it);
                pv[j] = *reinterpret_cast<const float2*>(g_P + (size_t)s * 64 + 2 * lane);
                qv[j] = *reinterpret_cast<const float2*>(g_Q + (size_t)d * 64 + 2 * lane);
            }
            #pragma unroll
            for (int j = 0; j < 8; j++) {
                const int it = b * 8 + j;
                const float sq = __shfl_sync(0xffffffffu, sqI, it);
                float h0 = fmaxf(pv[j].x + qv[j].x + sq * wl.x, 0.f);
                float h1 = fmaxf(pv[j].y + qv[j].y + sq * wl.y, 0.f);
                __half2 hv = __floats2half2_rn(h0, h1);
                A[(pw * 16 + it) * 36 + kposl] = *reinterpret_cast<uint32_t*>(&hv);
            }
        }
    };

    // ---------------- consumer constants ----------------
    const int g  = lane >> 2;
    const int l4 = lane & 3;
    const int eb = wid * 16;
    const bool even = !(l4 & 1);

    if (wid >= 4) fill(reinterpret_cast<uint32_t*>(sm) + O_A0, blockIdx.x);
    __syncthreads();

    int buf = 0;
    for (int t = blockIdx.x; t < N_TILES; t += NCTAS) {
        if (wid >= 4) {
            const int tn = t + NCTAS;
            if (tn < N_TILES)
                fill(reinterpret_cast<uint32_t*>(sm) + (buf ? O_A0 : O_A1), tn);
        } else {
            const uint32_t* Au =
                reinterpret_cast<const uint32_t*>(sm) + (buf ? O_A1 : O_A0);
            const uint32_t* W2u = reinterpret_cast<const uint32_t*>(sm) + O_W2F;

            // -------- layer 2: 4 k16-steps, 32 HMMA --------
            float acc[8][4];
            #pragma unroll
            for (int ct = 0; ct < 8; ct++)
                acc[ct][0] = acc[ct][1] = acc[ct][2] = acc[ct][3] = 0.f;

            #pragma unroll
            for (int kk = 0; kk < 4; kk++) {
                const int ko = kk * 8 + 2 * l4;
                uint2 alo = *reinterpret_cast<const uint2*>(Au + (eb + g) * 36 + ko);
                uint2 ahi = *reinterpret_cast<const uint2*>(Au + (eb + g + 8) * 36 + ko);
                #pragma unroll
                for (int ct = 0; ct < 8; ct++) {
                    uint2 bv = *reinterpret_cast<const uint2*>(
                        W2u + (ct * 8 + g) * 36 + ko);
                    mma16h(acc[ct], alo.x, ahi.x, alo.y, ahi.y, bv.x, bv.y);
                }
            }

            // -------- epilogue: m = relu(d2+b2) in-place, gate --------
            float pg = 0.f, pg8 = 0.f;
            #pragma unroll
            for (int ct = 0; ct < 8; ct++) {
                const int c0 = ct * 8 + 2 * l4;
                const float bb0 = sm[O_B2 + c0], bb1 = sm[O_B2 + c0 + 1];
                const float w0 = sm[O_WE + c0],  w1 = sm[O_WE + c0 + 1];
                acc[ct][0] = fmaxf(acc[ct][0] + bb0, 0.f);
                acc[ct][1] = fmaxf(acc[ct][1] + bb1, 0.f);
                acc[ct][2] = fmaxf(acc[ct][2] + bb0, 0.f);
                acc[ct][3] = fmaxf(acc[ct][3] + bb1, 0.f);
                pg  = fmaf(acc[ct][0], w0, fmaf(acc[ct][1], w1, pg));
                pg8 = fmaf(acc[ct][2], w0, fmaf(acc[ct][3], w1, pg8));
            }
            pg  += __shfl_xor_sync(0xffffffffu, pg, 1);
            pg  += __shfl_xor_sync(0xffffffffu, pg, 2);
            pg8 += __shfl_xor_sync(0xffffffffu, pg8, 1);
            pg8 += __shfl_xor_sync(0xffffffffu, pg8, 2);
            const float be0 = sm[O_BE];
            const float G  = 1.f / (1.f + __expf(-(pg + be0)));
            const float G8 = 1.f / (1.f + __expf(-(pg8 + be0)));

            // -------- scatter: ct-pairs -> full-width red4 --------
            const int dg  = dst[t * TILE_E + eb + g];
            const int dg8 = dst[t * TILE_E + eb + g + 8];
            float* bp  = g_msum + (size_t)dg * 64;
            float* bp8 = g_msum + (size_t)dg8 * 64;
            #pragma unroll
            for (int a = 0; a < 4; a++) {
                const int ct0 = 2 * a, ct1 = 2 * a + 1;
                float s00 = acc[ct0][0] * G,  s01 = acc[ct0][1] * G;
                float s02 = acc[ct0][2] * G8, s03 = acc[ct0][3] * G8;
                float s10 = acc[ct1][0] * G,  s11 = acc[ct1][1] * G;
                float s12 = acc[ct1][2] * G8, s13 = acc[ct1][3] * G8;
                float x0 = __shfl_xor_sync(0xffffffffu, s00, 1);
                float x1 = __shfl_xor_sync(0xffffffffu, s01, 1);
                float x2 = __shfl_xor_sync(0xffffffffu, s02, 1);
                float x3 = __shfl_xor_sync(0xffffffffu, s03, 1);
                float y0 = __shfl_xor_sync(0xffffffffu, s10, 1);
                float y1 = __shfl_xor_sync(0xffffffffu, s11, 1);
                float y2 = __shfl_xor_sync(0xffffffffu, s12, 1);
                float y3 = __shfl_xor_sync(0xffffffffu, s13, 1);
                const int chb = (even ? ct0 : ct1) * 8 + 2 * (l4 & ~1);
                float a0 = even ? s00 : y0,  a1 = even ? s01 : y1;
                float a2 = even ? x0  : s10, a3 = even ? x1  : s11;
                float b0 = even ? s02 : y2,  b1 = even ? s03 : y3;
                float b2 = even ? x2  : s12, b3 = even ? x3  : s13;
                red4(bp + chb,  a0, a1, a2, a3);
                red4(bp8 + chb, b0, b1, b2, b3);
            }
        }
        __syncthreads();
        buf ^= 1;
    }
}

// ---------------------------------------------------------------------------
// node_kernel: HMMA tf32, H overlays A (halved smem -> 3 CTA/SM, 1 wave).
//   out = relu((msum+feat)@U1 + c1) @ U2 + c2 + feat
// ---------------------------------------------------------------------------
#define NODE_SMEM_WORDS (4352 + 4352 + 64 + 64 + 8 * 1088)
#define NODE_SMEM_BYTES (NODE_SMEM_WORDS * 4)   // 70,144

__global__ __launch_bounds__(256, 3) void node_kernel(
    const float* __restrict__ feat,
    const float* __restrict__ U1, const float* __restrict__ c1,
    const float* __restrict__ U2, const float* __restrict__ c2,
    float* __restrict__ out)
{
    extern __shared__ float ns[];
    float* sU1 = ns;
    float* sU2 = ns + 4352;
    float* sc1 = ns + 8704;
    float* sc2 = ns + 8768;
    const int tid = threadIdx.x;
    const int w   = tid >> 5;
    const int l   = tid & 31;
    const int g   = l >> 2;
    const int l4  = l & 3;
    uint32_t* pA = reinterpret_cast<uint32_t*>(ns + 8832 + w * 1088);

    for (int i = tid; i < 64 * 64; i += 256) {
        int k = i >> 6, n = i & 63;
        reinterpret_cast<uint32_t*>(sU1)[n * 68 + kpos(k)] = tf32r(U1[i]);
        reinterpret_cast<uint32_t*>(sU2)[n * 68 + kpos(k)] = tf32r(U2[i]);
    }
    if (tid < 64) { sc1[tid] = c1[tid]; sc2[tid] = c2[tid]; }
    __syncthreads();

    for (int grp = blockIdx.x * 8 + w; grp < NGRP; grp += gridDim.x * 8) {
        const int n0 = grp * 16;
        #pragma unroll 4
        for (int r = 0; r < 16; r++) {
            float2 ms = *reinterpret_cast<const float2*>(
                g_msum + (size_t)(n0 + r) * 64 + 2 * l);
            float2 f = *reinterpret_cast<const float2*>(
                feat + (size_t)(n0 + r) * 64 + 2 * l);
            uint32_t* row = pA + r * 68;
            row[kpos(2 * l)]     = tf32r(ms.x + f.x);
            row[kpos(2 * l + 1)] = tf32r(ms.y + f.y);
        }
        __syncwarp();

        // layer 1
        float acc[8][4];
        #pragma unroll
        for (int ct = 0; ct < 8; ct++)
            acc[ct][0] = acc[ct][1] = acc[ct][2] = acc[ct][3] = 0.f;
        #pragma unroll
        for (int kk = 0; kk < 8; kk++) {
            const int ko = kk * 8 + 2 * l4;
            uint2 alo = *reinterpret_cast<const uint2*>(pA + g * 68 + ko);
            uint2 ahi = *reinterpret_cast<const uint2*>(pA + (g + 8) * 68 + ko);
            #pragma unroll
            for (int ct = 0; ct < 8; ct++) {
                uint2 bv = *reinterpret_cast<const uint2*>(
                    reinterpret_cast<uint32_t*>(sU1) + (ct * 8 + g) * 68 + ko);
                mma8(acc[ct], alo.x, ahi.x, alo.y, ahi.y, bv.x, bv.y);
            }
        }
        __syncwarp();   // all A reads done before overwrite
        // epilogue 1: relu -> H (overlays A)
        #pragma unroll
        for (int ct = 0; ct < 8; ct++) {
            const int c0 = ct * 8 + 2 * l4;
            const float bb0 = sc1[c0], bb1 = sc1[c0 + 1];
            pA[g * 68 + kpos(c0)]           = tf32r(fmaxf(acc[ct][0] + bb0, 0.f));
            pA[g * 68 + kpos(c0 + 1)]       = tf32r(fmaxf(acc[ct][1] + bb1, 0.f));
            pA[(g + 8) * 68 + kpos(c0)]     = tf32r(fmaxf(acc[ct][2] + bb0, 0.f));
            pA[(g + 8) * 68 + kpos(c0 + 1)] = tf32r(fmaxf(acc[ct][3] + bb1, 0.f));
        }
        __syncwarp();

        // layer 2
        #pragma unroll
        for (int ct = 0; ct < 8; ct++)
            acc[ct][0] = acc[ct][1] = acc[ct][2] = acc[ct][3] = 0.f;
        #pragma unroll
        for (int kk = 0; kk < 8; kk++) {
            const int ko = kk * 8 + 2 * l4;
            uint2 alo = *reinterpret_cast<const uint2*>(pA + g * 68 + ko);
            uint2 ahi = *reinterpret_cast<const uint2*>(pA + (g + 8) * 68 + ko);
            #pragma unroll
            for (int ct = 0; ct < 8; ct++) {
                uint2 bv = *reinterpret_cast<const uint2*>(
                    reinterpret_cast<uint32_t*>(sU2) + (ct * 8 + g) * 68 + ko);
                mma8(acc[ct], alo.x, ahi.x, alo.y, ahi.y, bv.x, bv.y);
            }
        }
        // epilogue 2: + c2 + feat residual
        #pragma unroll
        for (int ct = 0; ct < 8; ct++) {
            const int c0 = ct * 8 + 2 * l4;
            const float bb0 = sc2[c0], bb1 = sc2[c0 + 1];
            float2 f0 = *reinterpret_cast<const float2*>(
                feat + (size_t)(n0 + g) * 64 + c0);
            float2 f1 = *reinterpret_cast<const float2*>(
                feat + (size_t)(n0 + g + 8) * 64 + c0);
            *reinterpret_cast<float2*>(out + (size_t)(n0 + g) * 64 + c0) =
                make_float2(acc[ct][0] + bb0 + f0.x, acc[ct][1] + bb1 + f0.y);
            *reinterpret_cast<float2*>(out + (size_t)(n0 + g + 8) * 64 + c0) =
                make_float2(acc[ct][2] + bb0 + f1.x, acc[ct][3] + bb1 + f1.y);
        }
        __syncwarp();
    }
}

// ---------------------------------------------------------------------------
extern "C" void kernel_launch(void* const* d_in, const int* in_sizes, int n_in,
                              void* d_out, int out_size)
{
    const float* feat = (const float*)d_in[0];
    const float* x    = (const float*)d_in[1];
    const int*   src  = (const int*)  d_in[2];
    const int*   dst  = (const int*)  d_in[3];
    const float* W1   = (const float*)d_in[4];
    const float* b1   = (const float*)d_in[5];
    const float* W2   = (const float*)d_in[6];
    const float* b2   = (const float*)d_in[7];
    const float* we   = (const float*)d_in[8];
    const float* be   = (const float*)d_in[9];
    const float* U1   = (const float*)d_in[10];
    const float* c1   = (const float*)d_in[11];
    const float* U2   = (const float*)d_in[12];
    const float* c2   = (const float*)d_in[13];
    float* out = (float*)d_out;

    cudaFuncSetAttribute(pq_kernel,
                         cudaFuncAttributeMaxDynamicSharedMemorySize,
                         PQ_SMEM_BYTES);
    cudaFuncSetAttribute(node_kernel,
                         cudaFuncAttributeMaxDynamicSharedMemorySize,
                         NODE_SMEM_BYTES);

    zs_kernel<<<1184, 256>>>(x, src, dst);
    pq_kernel<<<456, 256, PQ_SMEM_BYTES>>>(feat, W1, b1);
    edge_kernel<<<NCTAS, 256>>>(src, dst, W1, W2, b2, we, be);
    node_kernel<<<456, 256, NODE_SMEM_BYTES>>>(feat, U1, c1, U2, c2, out);
}

// round 11
// speedup vs baseline: 10.6266x; 1.0891x over previous
#include <cuda_runtime.h>
#include <cuda_fp16.h>
#include <math.h>
#include <cstdint>

#define N_NODES 50000
#define N_EDGES 800000
#define TILE_E  64
#define N_TILES (N_EDGES / TILE_E)   // 12500
#define NCTAS   456                  // edge: 3 per SM
#define NGRP    (N_NODES / 16)       // 3125 exact

// Device scratch (no allocs allowed).
__device__ float    g_msum[N_NODES * 64];
__device__ uint32_t g_Ph[N_NODES * 32];   // half2: feat@W1a + b1
__device__ uint32_t g_Qh[N_NODES * 32];   // half2: feat@W1b
__device__ float    g_sqd[N_EDGES];

// fragment permutation within each 8-slot group
__host__ __device__ __forceinline__ int kpos(int s) {
    return (s & ~7) + 2 * (s & 3) + ((s >> 2) & 1);
}
__device__ __forceinline__ void mma16h(float d[4], uint32_t a0, uint32_t a1,
                                       uint32_t a2, uint32_t a3,
                                       uint32_t b0, uint32_t b1) {
    asm("mma.sync.aligned.m16n8k16.row.col.f32.f16.f16.f32 "
        "{%0,%1,%2,%3}, {%4,%5,%6,%7}, {%8,%9}, {%0,%1,%2,%3};"
        : "+f"(d[0]), "+f"(d[1]), "+f"(d[2]), "+f"(d[3])
        : "r"(a0), "r"(a1), "r"(a2), "r"(a3), "r"(b0), "r"(b1));
}
__device__ __forceinline__ void red4(float* p, float a, float b, float c, float d) {
    asm volatile("red.global.add.v4.f32 [%0], {%1,%2,%3,%4};"
                 :: "l"(p), "f"(a), "f"(b), "f"(c), "f"(d) : "memory");
}
__device__ __forceinline__ uint32_t h2pack(float a, float b) {
    __half2 hv = __floats2half2_rn(a, b);
    return *reinterpret_cast<uint32_t*>(&hv);
}
__device__ __forceinline__ float2 h2unpack(uint32_t u) {
    return __half22float2(*reinterpret_cast<__half2*>(&u));
}

// ---------------------------------------------------------------------------
// pq_kernel: prologue (zero g_msum + per-edge sqd), then
// [Ph|Qh] = feat @ [W1a|W1b] via HMMA fp16, two B-half passes.
// smem (words): sW [128][36]=4608 | sb1 64 | per-warp A [16][36] x 8 = 4608
// ---------------------------------------------------------------------------
#define PQ_SMEM_WORDS (4608 + 64 + 8 * 576)
#define PQ_SMEM_BYTES (PQ_SMEM_WORDS * 4)    // 37,120

__global__ __launch_bounds__(256, 4) void pq_kernel(
    const float* __restrict__ feat, const float* __restrict__ x,
    const int* __restrict__ src, const int* __restrict__ dst,
    const float* __restrict__ W1, const float* __restrict__ b1)
{
    extern __shared__ uint32_t ps[];
    uint32_t* sW  = ps;                                   // f16 B layout
    float*    sb1 = reinterpret_cast<float*>(ps + 4608);
    const int tid = threadIdx.x;
    const int w   = tid >> 5;
    const int l   = tid & 31;
    const int g   = l >> 2;
    const int l4  = l & 3;
    uint32_t* pA = ps + 4672 + w * 576;

    // weights: B[n][k], n<64 -> W1a (P), n>=64 -> W1b (Q); f16 word layout
    for (int i = tid; i < 128 * 64; i += 256) {
        int n = i >> 6, k = i & 63;
        float v = (n < 64) ? W1[k * 64 + n] : W1[(64 + k) * 64 + (n - 64)];
        __half* rowp = reinterpret_cast<__half*>(sW + n * 36);
        rowp[kpos(k >> 1) * 2 + (k & 1)] = __float2half(v);
    }
    if (tid < 64) sb1[tid] = b1[tid];

    // prologue: zero scatter accumulator + per-edge sqd
    const int gid = blockIdx.x * 256 + tid;
    const int gs  = gridDim.x * 256;
    for (int i = gid; i < N_NODES * 16; i += gs)
        reinterpret_cast<float4*>(g_msum)[i] = make_float4(0.f, 0.f, 0.f, 0.f);
    for (int e = gid; e < N_EDGES; e += gs) {
        const int s = src[e], d = dst[e];
        float dx = x[3 * s + 0] - x[3 * d + 0];
        float dy = x[3 * s + 1] - x[3 * d + 1];
        float dz = x[3 * s + 2] - x[3 * d + 2];
        g_sqd[e] = dx * dx + dy * dy + dz * dz;
    }
    __syncthreads();

    for (int grp = blockIdx.x * 8 + w; grp < NGRP; grp += gridDim.x * 8) {
        const int n0 = grp * 16;
        #pragma unroll 4
        for (int r = 0; r < 16; r++) {
            float2 f = *reinterpret_cast<const float2*>(
                feat + (size_t)(n0 + r) * 64 + 2 * l);
            pA[r * 36 + kpos(l)] = h2pack(f.x, f.y);
        }
        __syncwarp();

        #pragma unroll
        for (int pass = 0; pass < 2; pass++) {
            float acc[8][4];
            #pragma unroll
            for (int ct = 0; ct < 8; ct++)
                acc[ct][0] = acc[ct][1] = acc[ct][2] = acc[ct][3] = 0.f;

            #pragma unroll
            for (int kk = 0; kk < 4; kk++) {
                const int ko = kk * 8 + 2 * l4;
                uint2 alo = *reinterpret_cast<const uint2*>(pA + g * 36 + ko);
                uint2 ahi = *reinterpret_cast<const uint2*>(pA + (g + 8) * 36 + ko);
                #pragma unroll
                for (int ct = 0; ct < 8; ct++) {
                    uint2 bv = *reinterpret_cast<const uint2*>(
                        sW + ((pass * 8 + ct) * 8 + g) * 36 + ko);
                    mma16h(acc[ct], alo.x, ahi.x, alo.y, ahi.y, bv.x, bv.y);
                }
            }

            uint32_t* dstbuf = pass ? g_Qh : g_Ph;
            #pragma unroll
            for (int ct = 0; ct < 8; ct++) {
                const int n = ct * 8 + 2 * l4;      // col pair (n, n+1)
                const float bb0 = pass ? 0.f : sb1[n];
                const float bb1 = pass ? 0.f : sb1[n + 1];
                const int j = ct * 4 + l4;          // word index n/2
                dstbuf[(size_t)(n0 + g) * 32 + j] =
                    h2pack(acc[ct][0] + bb0, acc[ct][1] + bb1);
                dstbuf[(size_t)(n0 + g + 8) * 32 + j] =
                    h2pack(acc[ct][2] + bb0, acc[ct][3] + bb1);
            }
        }
        __syncwarp();
    }
}

// ---------------------------------------------------------------------------
// Edge kernel: persistent, 3 CTAs/SM, 64-edge tiles.
//   warps 0-3: consumers — layer-2 HMMA fp16 + gate + full-width red4 scatter
//   warps 4-7: producers — h1 = relu(Ph[src]+Qh[dst]+sqd*wl), pipelined
// smem words: A0 [64][36]=2304 | A1 2304 | W2f [64][36]=2304 | misc
// ---------------------------------------------------------------------------
#define O_A0   0
#define O_A1   2304
#define O_W2F  4608
#define O_WL   6912
#define O_B2   6976
#define O_WE   7040
#define O_BE   7104
#define EDGE_SMEM_WORDS 7112   // 28,448 B static

__global__ __launch_bounds__(256, 3) void edge_kernel(
    const int* __restrict__ src, const int* __restrict__ dst,
    const float* __restrict__ W1, const float* __restrict__ W2,
    const float* __restrict__ b2, const float* __restrict__ we,
    const float* __restrict__ be)
{
    __shared__ float sm[EDGE_SMEM_WORDS];
    const int tid  = threadIdx.x;
    const int wid  = tid >> 5;
    const int lane = tid & 31;

    for (int i = tid; i < 64 * 64; i += 256) {
        int k = i >> 6, n = i & 63;
        __half* rowp = reinterpret_cast<__half*>(
            reinterpret_cast<uint32_t*>(sm) + O_W2F + n * 36);
        rowp[kpos(k >> 1) * 2 + (k & 1)] = __float2half(W2[i]);
    }
    if (tid < 64) {
        sm[O_WL + tid] = W1[128 * 64 + tid];
        sm[O_B2 + tid] = b2[tid];
        sm[O_WE + tid] = we[tid];
    }
    if (tid == 0) sm[O_BE] = be[0];
    __syncthreads();

    // ---------------- producer (software-pipelined, half2 gathers) ----------
    const int pw    = wid - 4;
    const int kposl = kpos(lane);
    auto fill = [&](uint32_t* A, int t) {
        const float2 wl = *reinterpret_cast<const float2*>(sm + O_WL + 2 * lane);
        const int e0 = t * TILE_E + pw * 16;
        int   sI = 0, dI = 0;
        float sqI = 0.f;
        if (lane < 16) {
            sI  = src[e0 + lane];
            dI  = dst[e0 + lane];
            sqI = g_sqd[e0 + lane];
        }
        #pragma unroll
        for (int b = 0; b < 2; b++) {
            uint32_t pv[8], qv[8];
            #pragma unroll
            for (int j = 0; j < 8; j++) {
                const int it = b * 8 + j;
                const int s = __shfl_sync(0xffffffffu, sI, it);
                const int d = __shfl_sync(0xffffffffu, dI, it);
                pv[j] = g_Ph[(size_t)s * 32 + lane];
                qv[j] = g_Qh[(size_t)d * 32 + lane];
            }
            #pragma unroll
            for (int j = 0; j < 8; j++) {
                const int it = b * 8 + j;
                const float sq = __shfl_sync(0xffffffffu, sqI, it);
                float2 p2 = h2unpack(pv[j]);
                float2 q2 = h2unpack(qv[j]);
                float h0 = fmaxf(p2.x + q2.x + sq * wl.x, 0.f);
                float h1 = fmaxf(p2.y + q2.y + sq * wl.y, 0.f);
                A[(pw * 16 + it) * 36 + kposl] = h2pack(h0, h1);
            }
        }
    };

    // ---------------- consumer constants ----------------
    const int g  = lane >> 2;
    const int l4 = lane & 3;
    const int eb = wid * 16;
    const bool even = !(l4 & 1);

    if (wid >= 4) fill(reinterpret_cast<uint32_t*>(sm) + O_A0, blockIdx.x);
    __syncthreads();

    int buf = 0;
    for (int t = blockIdx.x; t < N_TILES; t += NCTAS) {
        if (wid >= 4) {
            const int tn = t + NCTAS;
            if (tn < N_TILES)
                fill(reinterpret_cast<uint32_t*>(sm) + (buf ? O_A0 : O_A1), tn);
        } else {
            const uint32_t* Au =
                reinterpret_cast<const uint32_t*>(sm) + (buf ? O_A1 : O_A0);
            const uint32_t* W2u = reinterpret_cast<const uint32_t*>(sm) + O_W2F;

            float acc[8][4];
            #pragma unroll
            for (int ct = 0; ct < 8; ct++)
                acc[ct][0] = acc[ct][1] = acc[ct][2] = acc[ct][3] = 0.f;

            #pragma unroll
            for (int kk = 0; kk < 4; kk++) {
                const int ko = kk * 8 + 2 * l4;
                uint2 alo = *reinterpret_cast<const uint2*>(Au + (eb + g) * 36 + ko);
                uint2 ahi = *reinterpret_cast<const uint2*>(Au + (eb + g + 8) * 36 + ko);
                #pragma unroll
                for (int ct = 0; ct < 8; ct++) {
                    uint2 bv = *reinterpret_cast<const uint2*>(
                        W2u + (ct * 8 + g) * 36 + ko);
                    mma16h(acc[ct], alo.x, ahi.x, alo.y, ahi.y, bv.x, bv.y);
                }
            }

            float pg = 0.f, pg8 = 0.f;
            #pragma unroll
            for (int ct = 0; ct < 8; ct++) {
                const int c0 = ct * 8 + 2 * l4;
                const float bb0 = sm[O_B2 + c0], bb1 = sm[O_B2 + c0 + 1];
                const float w0 = sm[O_WE + c0],  w1 = sm[O_WE + c0 + 1];
                acc[ct][0] = fmaxf(acc[ct][0] + bb0, 0.f);
                acc[ct][1] = fmaxf(acc[ct][1] + bb1, 0.f);
                acc[ct][2] = fmaxf(acc[ct][2] + bb0, 0.f);
                acc[ct][3] = fmaxf(acc[ct][3] + bb1, 0.f);
                pg  = fmaf(acc[ct][0], w0, fmaf(acc[ct][1], w1, pg));
                pg8 = fmaf(acc[ct][2], w0, fmaf(acc[ct][3], w1, pg8));
            }
            pg  += __shfl_xor_sync(0xffffffffu, pg, 1);
            pg  += __shfl_xor_sync(0xffffffffu, pg, 2);
            pg8 += __shfl_xor_sync(0xffffffffu, pg8, 1);
            pg8 += __shfl_xor_sync(0xffffffffu, pg8, 2);
            const float be0 = sm[O_BE];
            const float G  = 1.f / (1.f + __expf(-(pg + be0)));
            const float G8 = 1.f / (1.f + __expf(-(pg8 + be0)));

            const int dg  = dst[t * TILE_E + eb + g];
            const int dg8 = dst[t * TILE_E + eb + g + 8];
            float* bp  = g_msum + (size_t)dg * 64;
            float* bp8 = g_msum + (size_t)dg8 * 64;
            #pragma unroll
            for (int a = 0; a < 4; a++) {
                const int ct0 = 2 * a, ct1 = 2 * a + 1;
                float s00 = acc[ct0][0] * G,  s01 = acc[ct0][1] * G;
                float s02 = acc[ct0][2] * G8, s03 = acc[ct0][3] * G8;
                float s10 = acc[ct1][0] * G,  s11 = acc[ct1][1] * G;
                float s12 = acc[ct1][2] * G8, s13 = acc[ct1][3] * G8;
                float x0 = __shfl_xor_sync(0xffffffffu, s00, 1);
                float x1 = __shfl_xor_sync(0xffffffffu, s01, 1);
                float x2 = __shfl_xor_sync(0xffffffffu, s02, 1);
                float x3 = __shfl_xor_sync(0xffffffffu, s03, 1);
                float y0 = __shfl_xor_sync(0xffffffffu, s10, 1);
                float y1 = __shfl_xor_sync(0xffffffffu, s11, 1);
                float y2 = __shfl_xor_sync(0xffffffffu, s12, 1);
                float y3 = __shfl_xor_sync(0xffffffffu, s13, 1);
                const int chb = (even ? ct0 : ct1) * 8 + 2 * (l4 & ~1);
                float a0 = even ? s00 : y0,  a1 = even ? s01 : y1;
                float a2 = even ? x0  : s10, a3 = even ? x1  : s11;
                float b0 = even ? s02 : y2,  b1 = even ? s03 : y3;
                float b2 = even ? x2  : s12, b3 = even ? x3  : s13;
                red4(bp + chb,  a0, a1, a2, a3);
                red4(bp8 + chb, b0, b1, b2, b3);
            }
        }
        __syncthreads();
        buf ^= 1;
    }
}

// ---------------------------------------------------------------------------
// node_kernel: HMMA fp16, H overlays A; 4 CTA/SM target.
//   out = relu((msum+feat)@U1 + c1) @ U2 + c2 + feat
// smem words: sU1h 2304 | sU2h 2304 | c1 64 | c2 64 | per-warp A 576 x 8
// ---------------------------------------------------------------------------
#define NODE_SMEM_WORDS (2304 + 2304 + 64 + 64 + 8 * 576)
#define NODE_SMEM_BYTES (NODE_SMEM_WORDS * 4)   // 37,376

__global__ __launch_bounds__(256, 4) void node_kernel(
    const float* __restrict__ feat,
    const float* __restrict__ U1, const float* __restrict__ c1,
    const float* __restrict__ U2, const float* __restrict__ c2,
    float* __restrict__ out)
{
    extern __shared__ uint32_t ns[];
    uint32_t* sU1h = ns;
    uint32_t* sU2h = ns + 2304;
    float*    sc1  = reinterpret_cast<float*>(ns + 4608);
    float*    sc2  = reinterpret_cast<float*>(ns + 4672);
    const int tid = threadIdx.x;
    const int w   = tid >> 5;
    const int l   = tid & 31;
    const int g   = l >> 2;
    const int l4  = l & 3;
    uint32_t* pA = ns + 4736 + w * 576;

    for (int i = tid; i < 64 * 64; i += 256) {
        int k = i >> 6, n = i & 63;
        reinterpret_cast<__half*>(sU1h + n * 36)[kpos(k >> 1) * 2 + (k & 1)] =
            __float2half(U1[i]);
        reinterpret_cast<__half*>(sU2h + n * 36)[kpos(k >> 1) * 2 + (k & 1)] =
            __float2half(U2[i]);
    }
    if (tid < 64) { sc1[tid] = c1[tid]; sc2[tid] = c2[tid]; }
    __syncthreads();

    for (int grp = blockIdx.x * 8 + w; grp < NGRP; grp += gridDim.x * 8) {
        const int n0 = grp * 16;
        #pragma unroll 4
        for (int r = 0; r < 16; r++) {
            float2 ms = *reinterpret_cast<const float2*>(
                g_msum + (size_t)(n0 + r) * 64 + 2 * l);
            float2 f = *reinterpret_cast<const float2*>(
                feat + (size_t)(n0 + r) * 64 + 2 * l);
            pA[r * 36 + kpos(l)] = h2pack(ms.x + f.x, ms.y + f.y);
        }
        __syncwarp();

        // layer 1
        float acc[8][4];
        #pragma unroll
        for (int ct = 0; ct < 8; ct++)
            acc[ct][0] = acc[ct][1] = acc[ct][2] = acc[ct][3] = 0.f;
        #pragma unroll
        for (int kk = 0; kk < 4; kk++) {
            const int ko = kk * 8 + 2 * l4;
            uint2 alo = *reinterpret_cast<const uint2*>(pA + g * 36 + ko);
            uint2 ahi = *reinterpret_cast<const uint2*>(pA + (g + 8) * 36 + ko);
            #pragma unroll
            for (int ct = 0; ct < 8; ct++) {
                uint2 bv = *reinterpret_cast<const uint2*>(
                    sU1h + (ct * 8 + g) * 36 + ko);
                mma16h(acc[ct], alo.x, ahi.x, alo.y, ahi.y, bv.x, bv.y);
            }
        }
        __syncwarp();   // A reads complete before overwrite
        // epilogue 1: relu -> H (overlays A)
        #pragma unroll
        for (int ct = 0; ct < 8; ct++) {
            const int c0 = ct * 8 + 2 * l4;
            const int j  = ct * 4 + l4;             // word index c0/2
            const float bb0 = sc1[c0], bb1 = sc1[c0 + 1];
            pA[g * 36 + kpos(j)] =
                h2pack(fmaxf(acc[ct][0] + bb0, 0.f), fmaxf(acc[ct][1] + bb1, 0.f));
            pA[(g + 8) * 36 + kpos(j)] =
                h2pack(fmaxf(acc[ct][2] + bb0, 0.f), fmaxf(acc[ct][3] + bb1, 0.f));
        }
        __syncwarp();

        // layer 2
        #pragma unroll
        for (int ct = 0; ct < 8; ct++)
            acc[ct][0] = acc[ct][1] = acc[ct][2] = acc[ct][3] = 0.f;
        #pragma unroll
        for (int kk = 0; kk < 4; kk++) {
            const int ko = kk * 8 + 2 * l4;
            uint2 alo = *reinterpret_cast<const uint2*>(pA + g * 36 + ko);
            uint2 ahi = *reinterpret_cast<const uint2*>(pA + (g + 8) * 36 + ko);
            #pragma unroll
            for (int ct = 0; ct < 8; ct++) {
                uint2 bv = *reinterpret_cast<const uint2*>(
                    sU2h + (ct * 8 + g) * 36 + ko);
                mma16h(acc[ct], alo.x, ahi.x, alo.y, ahi.y, bv.x, bv.y);
            }
        }
        // epilogue 2: + c2 + feat residual (fp32 out)
        #pragma unroll
        for (int ct = 0; ct < 8; ct++) {
            const int c0 = ct * 8 + 2 * l4;
            const float bb0 = sc2[c0], bb1 = sc2[c0 + 1];
            float2 f0 = *reinterpret_cast<const float2*>(
                feat + (size_t)(n0 + g) * 64 + c0);
            float2 f1 = *reinterpret_cast<const float2*>(
                feat + (size_t)(n0 + g + 8) * 64 + c0);
            *reinterpret_cast<float2*>(out + (size_t)(n0 + g) * 64 + c0) =
                make_float2(acc[ct][0] + bb0 + f0.x, acc[ct][1] + bb1 + f0.y);
            *reinterpret_cast<float2*>(out + (size_t)(n0 + g + 8) * 64 + c0) =
                make_float2(acc[ct][2] + bb0 + f1.x, acc[ct][3] + bb1 + f1.y);
        }
        __syncwarp();
    }
}

// ---------------------------------------------------------------------------
extern "C" void kernel_launch(void* const* d_in, const int* in_sizes, int n_in,
                              void* d_out, int out_size)
{
    const float* feat = (const float*)d_in[0];
    const float* x    = (const float*)d_in[1];
    const int*   src  = (const int*)  d_in[2];
    const int*   dst  = (const int*)  d_in[3];
    const float* W1   = (const float*)d_in[4];
    const float* b1   = (const float*)d_in[5];
    const float* W2   = (const float*)d_in[6];
    const float* b2   = (const float*)d_in[7];
    const float* we   = (const float*)d_in[8];
    const float* be   = (const float*)d_in[9];
    const float* U1   = (const float*)d_in[10];
    const float* c1   = (const float*)d_in[11];
    const float* U2   = (const float*)d_in[12];
    const float* c2   = (const float*)d_in[13];
    float* out = (float*)d_out;

    cudaFuncSetAttribute(pq_kernel,
                         cudaFuncAttributeMaxDynamicSharedMemorySize,
                         PQ_SMEM_BYTES);
    cudaFuncSetAttribute(node_kernel,
                         cudaFuncAttributeMaxDynamicSharedMemorySize,
                         NODE_SMEM_BYTES);

    pq_kernel<<<592, 256, PQ_SMEM_BYTES>>>(feat, x, src, dst, W1, b1);
    edge_kernel<<<NCTAS, 256>>>(src, dst, W1, W2, b2, we, be);
    node_kernel<<<592, 256, NODE_SMEM_BYTES>>>(feat, U1, c1, U2, c2, out);
}